// round 4
// baseline (speedup 1.0000x reference)
#include <cuda_runtime.h>

// Problem constants
#define B_ 256
#define H_ 512
#define C_ 64
#define NKNOTS 100
#define KTERMS 8

// Persistent GEMM tiling: 32x32 CTA tile, BK=32, 256 threads, per-thread 2x2.
// Grid = (256/32) x (512/32) = 8 x 16 = 128 CTAs (single wave on 148 SMs).
#define BM 32
#define BN 32
#define BK 32
#define TPB 256
#define NCTA 128
#define AST 34   // As row stride (floats), 8B-aligned rows
#define BST 68   // Bs(dup) row stride (floats), 16B-aligned rows
#define PIPE 4

typedef unsigned long long ull;

// Scratch (device globals; no allocation allowed)
__device__ float g_x[B_ * C_];
__device__ float g_xdot[B_ * C_];
__device__ float g_relu[B_ * H_];
__device__ float g_u[B_ * H_];
__device__ float g_curr[B_ * H_];

// grid-wide barrier state (generation scheme; count self-resets)
__device__ unsigned g_bar_count;
__device__ unsigned g_bar_gen;

// ---------------------------------------------------------------------------
__device__ __forceinline__ void ffma2(ull& d, ull a, ull b) {
    asm("fma.rn.f32x2 %0, %1, %2, %3;" : "=l"(d) : "l"(a), "l"(b), "l"(d));
}
__device__ __forceinline__ float2 upk2(ull v) {
    float2 f; asm("mov.b64 {%0, %1}, %2;" : "=f"(f.x), "=f"(f.y) : "l"(v)); return f;
}

// ---------------------------------------------------------------------------
// Grid-wide barrier. All 128 CTAs resident (<= 148 SMs, 1 CTA/SM).
// ---------------------------------------------------------------------------
__device__ __forceinline__ void gbar(unsigned& gen) {
    __syncthreads();
    if (threadIdx.x == 0) {
        __threadfence();
        unsigned old = atomicAdd(&g_bar_count, 1);
        if (old == NCTA - 1) {
            g_bar_count = 0;
            __threadfence();
            atomicAdd(&g_bar_gen, 1);
        } else {
            while (*((volatile unsigned*)&g_bar_gen) == gen) { }
        }
        __threadfence();
        gen++;
    }
    __syncthreads();
}

// ---------------------------------------------------------------------------
// Core NT GEMM: acc += A(BMxK) * W(BNxK)^T for this CTA's 32x32 tile.
// Per-thread 2x2: rows (2ty,2ty+1) packed in one FFMA2 lane pair, cols 2tx+{0,1}.
// B stored duplicated in smem: Bs[k][2n]=Bs[k][2n+1]=W[n][k] -> one LDS.128
// yields both (b,b) pairs. A pairs come straight from LDS.64. Zero pack MOVs.
// Double-buffered tiles, 4-deep LDS prefetch ring.
// CG: load A via L2 (cross-CTA data, L1 may be stale). DUAL: second A matrix.
// ---------------------------------------------------------------------------
template <bool CG, bool DUAL>
__device__ __forceinline__ void gemm32(const float* __restrict__ A1,
                                       const float* __restrict__ A2,
                                       const float* __restrict__ W, int K,
                                       float (*As)[BK][AST],
                                       float (*Xs)[BK][AST],
                                       float (*Bs)[BK][BST],
                                       ull acc1[2], ull acc2[2]) {
    const int tid  = threadIdx.x;
    const int lrow = tid >> 3;          // 0..31
    const int lk4  = (tid & 7) << 2;    // 0,4,...,28
    const int ty   = tid >> 4;          // 0..15
    const int tx   = tid & 15;          // 0..15

    const float* a1p = A1 + (size_t)lrow * K + lk4;
    const float* a2p = DUAL ? (A2 + (size_t)lrow * K + lk4) : A1;
    const float* wp  = W + (size_t)lrow * K + lk4;

    float4 pa = CG ? __ldcg((const float4*)a1p) : __ldg((const float4*)a1p);
    float4 px;
    if (DUAL) px = CG ? __ldcg((const float4*)a2p) : __ldg((const float4*)a2p);
    float4 pb = __ldg((const float4*)wp);

    const int NT = K / BK;
    // store stage 0
#pragma unroll
    for (int i = 0; i < 4; ++i) {
        As[0][lk4 + i][lrow] = (&pa.x)[i];
        if (DUAL) Xs[0][lk4 + i][lrow] = (&px.x)[i];
        *(float2*)&Bs[0][lk4 + i][2 * lrow] = make_float2((&pb.x)[i], (&pb.x)[i]);
    }
    __syncthreads();

    int buf = 0;
    for (int t = 0; t < NT; ++t, buf ^= 1) {
        if (t + 1 < NT) {
            int ko = (t + 1) * BK;
            pa = CG ? __ldcg((const float4*)(a1p + ko)) : __ldg((const float4*)(a1p + ko));
            if (DUAL) px = CG ? __ldcg((const float4*)(a2p + ko)) : __ldg((const float4*)(a2p + ko));
            pb = __ldg((const float4*)(wp + ko));
        }

        const float* asb = &As[buf][0][0] + 2 * ty;
        const float* xsb = &Xs[buf][0][0] + 2 * ty;
        const float* bsb = &Bs[buf][0][0] + 4 * tx;

        ull a_pre[PIPE], x_pre[PIPE];
        ulonglong2 b_pre[PIPE];
#pragma unroll
        for (int p = 0; p < PIPE; ++p) {
            a_pre[p] = *(const ull*)(asb + p * AST);
            if (DUAL) x_pre[p] = *(const ull*)(xsb + p * AST);
            b_pre[p] = *(const ulonglong2*)(bsb + p * BST);
        }
#pragma unroll
        for (int k = 0; k < BK; ++k) {
            ull a = a_pre[k & (PIPE - 1)];
            ulonglong2 b = b_pre[k & (PIPE - 1)];
            ull x;
            if (DUAL) x = x_pre[k & (PIPE - 1)];
            if (k + PIPE < BK) {
                a_pre[k & (PIPE - 1)] = *(const ull*)(asb + (k + PIPE) * AST);
                if (DUAL) x_pre[k & (PIPE - 1)] = *(const ull*)(xsb + (k + PIPE) * AST);
                b_pre[k & (PIPE - 1)] = *(const ulonglong2*)(bsb + (k + PIPE) * BST);
            }
            ffma2(acc1[0], a, b.x);
            ffma2(acc1[1], a, b.y);
            if (DUAL) {
                ffma2(acc2[0], x, b.x);
                ffma2(acc2[1], x, b.y);
            }
        }

        if (t + 1 < NT) {
#pragma unroll
            for (int i = 0; i < 4; ++i) {
                As[buf ^ 1][lk4 + i][lrow] = (&pa.x)[i];
                if (DUAL) Xs[buf ^ 1][lk4 + i][lrow] = (&px.x)[i];
                *(float2*)&Bs[buf ^ 1][lk4 + i][2 * lrow] =
                    make_float2((&pb.x)[i], (&pb.x)[i]);
            }
        }
        __syncthreads();
    }
}

// ---------------------------------------------------------------------------
// Single persistent fused kernel: spline + L1 + dtanh + 8 iterations.
// ---------------------------------------------------------------------------
__global__ __launch_bounds__(TPB, 1) void fused_kernel(
    const float* __restrict__ tptr, const float* __restrict__ tobs,
    const float* __restrict__ coeffs, const float* __restrict__ dcoeffs,
    const float* __restrict__ h,  const float* __restrict__ wx,
    const float* __restrict__ wh, const float* __restrict__ wout,
    const float* __restrict__ b0, const float* __restrict__ b1,
    float* __restrict__ out) {
    __shared__ __align__(16) float As[2][BK][AST];
    __shared__ __align__(16) float Xs[2][BK][AST];
    __shared__ __align__(16) float Bs[2][BK][BST];
    __shared__ float sdr[BM][BN + 1];  // drelu tile
    __shared__ float sdt[BM][BN + 1];  // dtanh tile

    const int tid = threadIdx.x;
    const int bm = blockIdx.x * BM;   // batch rows
    const int bn = blockIdx.y * BN;   // H cols
    const int ty = tid >> 4, tx = tid & 15;
    const int r0 = 2 * ty, c0 = 2 * tx;

    unsigned gen = 0;
    if (tid == 0) gen = *((volatile unsigned*)&g_bar_gen);

    // ---- Phase 0: spline eval (bn==0 CTAs handle their bm rows) ----
    if (blockIdx.y == 0) {
        __shared__ int s_idx;
        __shared__ float s_dt;
        if (tid == 0) {
            float tv = tptr[0];
            int cnt = 0;
            for (int i = 0; i < NKNOTS; i++) cnt += (tobs[i] <= tv) ? 1 : 0;
            int idx = min(max(cnt - 1, 0), NKNOTS - 2);
            s_idx = idx;
            s_dt = tv - tobs[idx];
        }
        __syncthreads();
        const int idx = s_idx;
        const float dt = s_dt;
        for (int e = tid; e < BM * C_; e += TPB) {
            int b = bm + e / C_;
            int c = e % C_;
            size_t base = ((size_t)(b * (NKNOTS - 1) + idx)) * 4 * C_ + c;
            float a0 = coeffs[base + 0 * C_], a1 = coeffs[base + 1 * C_];
            float a2 = coeffs[base + 2 * C_], a3 = coeffs[base + 3 * C_];
            __stcg(&g_x[b * C_ + c], a0 + dt * (a1 + dt * (a2 + dt * a3)));
            a0 = dcoeffs[base + 0 * C_]; a1 = dcoeffs[base + 1 * C_];
            a2 = dcoeffs[base + 2 * C_]; a3 = dcoeffs[base + 3 * C_];
            __stcg(&g_xdot[b * C_ + c], a0 + dt * (a1 + dt * (a2 + dt * a3)));
        }
    }

    const float bc0 = b0[bn + c0], bc1 = b0[bn + c0 + 1];
    const float bz0 = b1[bn + c0], bz1 = b1[bn + c0 + 1];

    // ---- Phase L1a: acc = h@wh^T (spline latency hidden behind this) ----
    ull acc[2] = {}, accw[2] = {};
    gemm32<false, false>(h + (size_t)bm * H_, nullptr, wh + (size_t)bn * H_,
                         H_, As, Xs, Bs, acc, accw);
    gbar(gen);  // spline results visible

    // ---- Phase L1b: acc += x@wx^T, accw = xdot@wx^T ----
    gemm32<true, true>(g_x + (size_t)bm * C_, g_xdot + (size_t)bm * C_,
                       wx + (size_t)bn * C_, C_, As, Xs, Bs, acc, accw);
    {
        float2 A0 = upk2(acc[0]), A1 = upk2(acc[1]);   // (.x=row r0, .y=row r1)
        float2 W0 = upk2(accw[0]), W1 = upk2(accw[1]);
        float l00 = A0.x + bc0, l01 = A1.x + bc1;      // row r0
        float l10 = A0.y + bc0, l11 = A1.y + bc1;      // row r1
        size_t o = (size_t)(bm + r0) * H_ + bn + c0;
        __stcg((float2*)&g_relu[o],      make_float2(fmaxf(l00, 0.f), fmaxf(l01, 0.f)));
        __stcg((float2*)&g_relu[o + H_], make_float2(fmaxf(l10, 0.f), fmaxf(l11, 0.f)));
        float d00 = 1.0f / (1.0f + expf(-l00)), d01 = 1.0f / (1.0f + expf(-l01));
        float d10 = 1.0f / (1.0f + expf(-l10)), d11 = 1.0f / (1.0f + expf(-l11));
        sdr[r0][c0] = d00; sdr[r0][c0 + 1] = d01;
        sdr[r0 + 1][c0] = d10; sdr[r0 + 1][c0 + 1] = d11;
        __stcg((float2*)&g_u[o],      make_float2(d00 * W0.x, d01 * W1.x));
        __stcg((float2*)&g_u[o + H_], make_float2(d10 * W0.y, d11 * W1.y));
    }
    gbar(gen);

    // ---- Phase D (dual): acc1 = relu@wout^T, acc2 = u0@wout^T ----
    ull z[2] = {}, uq[2] = {};
    gemm32<true, true>(g_relu + (size_t)bm * H_, g_u + (size_t)bm * H_,
                       wout + (size_t)bn * H_, H_, As, Xs, Bs, z, uq);
    float2 hd0, hd1;  // hdot for row r0 / r1 at cols (c0, c0+1)
    {
        float2 Z0 = upk2(z[0]), Z1 = upk2(z[1]);
        float2 U0 = upk2(uq[0]), U1 = upk2(uq[1]);
        float t00 = tanhf(Z0.x + bz0), t01 = tanhf(Z1.x + bz1);
        float t10 = tanhf(Z0.y + bz0), t11 = tanhf(Z1.y + bz1);
        float dt00 = 1.0f - t00 * t00, dt01 = 1.0f - t01 * t01;
        float dt10 = 1.0f - t10 * t10, dt11 = 1.0f - t11 * t11;
        sdt[r0][c0] = dt00; sdt[r0][c0 + 1] = dt01;
        sdt[r0 + 1][c0] = dt10; sdt[r0 + 1][c0 + 1] = dt11;
        hd0 = make_float2(dt00 * U0.x, dt01 * U1.x);
        hd1 = make_float2(dt10 * U0.y, dt11 * U1.y);
        size_t o = (size_t)(bm + r0) * H_ + bn + c0;
        __stcg((float2*)&g_curr[o], hd0);
        __stcg((float2*)&g_curr[o + H_], hd1);
    }
    gbar(gen);

    // ---- 8 von-Neumann iterations ----
    const size_t o = (size_t)(bm + r0) * H_ + bn + c0;
    for (int it = 0; it < KTERMS; ++it) {
        // u = drelu * (curr @ wh^T)
        ull a[2] = {};
        gemm32<true, false>(g_curr + (size_t)bm * H_, nullptr,
                            wh + (size_t)bn * H_, H_, As, Xs, Bs, a, uq);
        {
            float2 V0 = upk2(a[0]), V1 = upk2(a[1]);
            __stcg((float2*)&g_u[o],
                   make_float2(sdr[r0][c0] * V0.x, sdr[r0][c0 + 1] * V1.x));
            __stcg((float2*)&g_u[o + H_],
                   make_float2(sdr[r0 + 1][c0] * V0.y, sdr[r0 + 1][c0 + 1] * V1.y));
        }
        gbar(gen);

        // curr = dtanh * (u @ wout^T); hdot += curr
        ull c[2] = {};
        gemm32<true, false>(g_u + (size_t)bm * H_, nullptr,
                            wout + (size_t)bn * H_, H_, As, Xs, Bs, c, uq);
        {
            float2 V0 = upk2(c[0]), V1 = upk2(c[1]);
            float2 v0 = make_float2(sdt[r0][c0] * V0.x, sdt[r0][c0 + 1] * V1.x);
            float2 v1 = make_float2(sdt[r0 + 1][c0] * V0.y, sdt[r0 + 1][c0 + 1] * V1.y);
            hd0.x += v0.x; hd0.y += v0.y;
            hd1.x += v1.x; hd1.y += v1.y;
            if (it < KTERMS - 1) {
                __stcg((float2*)&g_curr[o], v0);
                __stcg((float2*)&g_curr[o + H_], v1);
                gbar(gen);
            }
        }
    }

    // ---- write h_dot ----
    *(float2*)&out[o] = hd0;
    *(float2*)&out[o + H_] = hd1;
}

// ---------------------------------------------------------------------------
extern "C" void kernel_launch(void* const* d_in, const int* in_sizes, int n_in,
                              void* d_out, int out_size) {
    const float* t      = (const float*)d_in[0];
    const float* h      = (const float*)d_in[1];
    const float* coeffs = (const float*)d_in[2];
    const float* dcoeff = (const float*)d_in[3];
    const float* tobs   = (const float*)d_in[4];
    const float* wx     = (const float*)d_in[5];
    const float* wh     = (const float*)d_in[6];
    const float* wout   = (const float*)d_in[7];
    const float* b0     = (const float*)d_in[8];
    const float* b1     = (const float*)d_in[9];
    float* out = (float*)d_out;

    dim3 grid(B_ / BM, H_ / BN);  // 8 x 16 = 128 CTAs, single wave
    fused_kernel<<<grid, TPB>>>(t, tobs, coeffs, dcoeff, h, wx, wh, wout,
                                b0, b1, out);
}

// round 5
// speedup vs baseline: 1.5713x; 1.5713x over previous
#include <cuda_runtime.h>

// Problem constants
#define B_ 256
#define H_ 512
#define C_ 64
#define NKNOTS 100
#define KTERMS 8

// Persistent GEMM tiling: 32x32 CTA tile, BK=32, 128 threads, per-thread 4x2.
// Grid = (256/32) x (512/32) = 8 x 16 = 128 CTAs (single wave on 148 SMs).
#define BM 32
#define BN 32
#define BK 32
#define TPB 128
#define NCTA 128
#define AST 36   // As row stride (floats): row byte offset 144 = 16B-aligned
#define BST 34   // Bs row stride (floats): row byte offset 136 = 8B-aligned
#define PIPE 4

typedef unsigned long long ull;

// Scratch (device globals; no allocation allowed)
__device__ float g_x[B_ * C_];
__device__ float g_xdot[B_ * C_];
__device__ float g_relu[B_ * H_];
__device__ float g_u[B_ * H_];
__device__ float g_curr[B_ * H_];

// grid-wide barrier state (generation scheme; count self-resets)
__device__ unsigned g_bar_count;
__device__ unsigned g_bar_gen;

// ---------------------------------------------------------------------------
__device__ __forceinline__ void ffma2(ull& d, ull a, ull b) {
    asm("fma.rn.f32x2 %0, %1, %2, %3;" : "=l"(d) : "l"(a), "l"(b), "l"(d));
}
__device__ __forceinline__ float2 upk2(ull v) {
    float2 f; asm("mov.b64 {%0, %1}, %2;" : "=f"(f.x), "=f"(f.y) : "l"(v)); return f;
}
__device__ __forceinline__ ull dup2(float b) {
    ull r; asm("mov.b64 %0, {%1, %1};" : "=l"(r) : "f"(b)); return r;
}

// ---------------------------------------------------------------------------
// Grid-wide barrier. All 128 CTAs resident (<= 148 SMs, 1 CTA/SM).
// ---------------------------------------------------------------------------
__device__ __forceinline__ void gbar(unsigned& gen) {
    __syncthreads();
    if (threadIdx.x == 0) {
        __threadfence();
        unsigned old = atomicAdd(&g_bar_count, 1);
        if (old == NCTA - 1) {
            g_bar_count = 0;
            __threadfence();
            atomicAdd(&g_bar_gen, 1);
        } else {
            while (*((volatile unsigned*)&g_bar_gen) == gen) { }
        }
        __threadfence();
        gen++;
    }
    __syncthreads();
}

// ---------------------------------------------------------------------------
// Core NT GEMM: acc[rp][j] += A(BMxK) * W(BNxK)^T, 32x32 CTA tile.
// 128 threads: ty=tid>>4 (rows 4ty..4ty+3), tx=tid&15 (cols 2tx, 2tx+1).
// Per k-step per thread: 1 LDS.128 (A, two natural f32x2 row pairs),
// 1 LDS.64 (B: b0,b1), 2 reg-dup MOVs, 4 FFMA2. Per warp: A=1 crossbar
// phase (broadcast), B=1 phase (128B) -> 8 phases/SM/k = FFMA2 floor.
// Double-buffered tiles, PIPE-deep LDS prefetch ring.
// CG: A loaded via L2 (cross-CTA data; L1 may be stale). DUAL: 2nd A matrix.
// ---------------------------------------------------------------------------
template <bool CG, bool DUAL>
__device__ __forceinline__ void gemm32(const float* __restrict__ A1,
                                       const float* __restrict__ A2,
                                       const float* __restrict__ W, int K,
                                       float (*As)[BK][AST],
                                       float (*Xs)[BK][AST],
                                       float (*Bs)[BK][BST],
                                       ull (*acc1)[2], ull (*acc2)[2]) {
    const int tid  = threadIdx.x;
    const int lrow = tid >> 3;          // 0..15
    const int lk4  = (tid & 7) << 2;    // 0,4,...,28
    const int ty   = tid >> 4;          // 0..7
    const int tx   = tid & 15;          // 0..15

    const float* a1p0 = A1 + (size_t)lrow * K + lk4;
    const float* a1p1 = A1 + (size_t)(lrow + 16) * K + lk4;
    const float* a2p0 = DUAL ? (A2 + (size_t)lrow * K + lk4) : A1;
    const float* a2p1 = DUAL ? (A2 + (size_t)(lrow + 16) * K + lk4) : A1;
    const float* wp0  = W + (size_t)lrow * K + lk4;
    const float* wp1  = W + (size_t)(lrow + 16) * K + lk4;

    float4 pa0 = CG ? __ldcg((const float4*)a1p0) : __ldg((const float4*)a1p0);
    float4 pa1 = CG ? __ldcg((const float4*)a1p1) : __ldg((const float4*)a1p1);
    float4 px0, px1;
    if (DUAL) {
        px0 = CG ? __ldcg((const float4*)a2p0) : __ldg((const float4*)a2p0);
        px1 = CG ? __ldcg((const float4*)a2p1) : __ldg((const float4*)a2p1);
    }
    float4 pb0 = __ldg((const float4*)wp0);
    float4 pb1 = __ldg((const float4*)wp1);

    const int NT = K / BK;
    // store stage 0
#pragma unroll
    for (int i = 0; i < 4; ++i) {
        As[0][lk4 + i][lrow]      = (&pa0.x)[i];
        As[0][lk4 + i][lrow + 16] = (&pa1.x)[i];
        if (DUAL) {
            Xs[0][lk4 + i][lrow]      = (&px0.x)[i];
            Xs[0][lk4 + i][lrow + 16] = (&px1.x)[i];
        }
        Bs[0][lk4 + i][lrow]      = (&pb0.x)[i];
        Bs[0][lk4 + i][lrow + 16] = (&pb1.x)[i];
    }
    __syncthreads();

    int buf = 0;
    for (int t = 0; t < NT; ++t, buf ^= 1) {
        if (t + 1 < NT) {
            int ko = (t + 1) * BK;
            pa0 = CG ? __ldcg((const float4*)(a1p0 + ko)) : __ldg((const float4*)(a1p0 + ko));
            pa1 = CG ? __ldcg((const float4*)(a1p1 + ko)) : __ldg((const float4*)(a1p1 + ko));
            if (DUAL) {
                px0 = CG ? __ldcg((const float4*)(a2p0 + ko)) : __ldg((const float4*)(a2p0 + ko));
                px1 = CG ? __ldcg((const float4*)(a2p1 + ko)) : __ldg((const float4*)(a2p1 + ko));
            }
            pb0 = __ldg((const float4*)(wp0 + ko));
            pb1 = __ldg((const float4*)(wp1 + ko));
        }

        const float* asb = &As[buf][0][4 * ty];
        const float* xsb = &Xs[buf][0][4 * ty];
        const float* bsb = &Bs[buf][0][2 * tx];

        ulonglong2 a_pre[PIPE], x_pre[PIPE];
        float2 b_pre[PIPE];
#pragma unroll
        for (int p = 0; p < PIPE; ++p) {
            a_pre[p] = *(const ulonglong2*)(asb + p * AST);
            if (DUAL) x_pre[p] = *(const ulonglong2*)(xsb + p * AST);
            b_pre[p] = *(const float2*)(bsb + p * BST);
        }
#pragma unroll
        for (int k = 0; k < BK; ++k) {
            ulonglong2 av = a_pre[k & (PIPE - 1)];
            float2 bv = b_pre[k & (PIPE - 1)];
            ulonglong2 xv;
            if (DUAL) xv = x_pre[k & (PIPE - 1)];
            if (k + PIPE < BK) {
                a_pre[k & (PIPE - 1)] = *(const ulonglong2*)(asb + (k + PIPE) * AST);
                if (DUAL) x_pre[k & (PIPE - 1)] = *(const ulonglong2*)(xsb + (k + PIPE) * AST);
                b_pre[k & (PIPE - 1)] = *(const float2*)(bsb + (k + PIPE) * BST);
            }
            ull bb0 = dup2(bv.x);
            ull bb1 = dup2(bv.y);
            ffma2(acc1[0][0], av.x, bb0);
            ffma2(acc1[0][1], av.x, bb1);
            ffma2(acc1[1][0], av.y, bb0);
            ffma2(acc1[1][1], av.y, bb1);
            if (DUAL) {
                ffma2(acc2[0][0], xv.x, bb0);
                ffma2(acc2[0][1], xv.x, bb1);
                ffma2(acc2[1][0], xv.y, bb0);
                ffma2(acc2[1][1], xv.y, bb1);
            }
        }

        if (t + 1 < NT) {
#pragma unroll
            for (int i = 0; i < 4; ++i) {
                As[buf ^ 1][lk4 + i][lrow]      = (&pa0.x)[i];
                As[buf ^ 1][lk4 + i][lrow + 16] = (&pa1.x)[i];
                if (DUAL) {
                    Xs[buf ^ 1][lk4 + i][lrow]      = (&px0.x)[i];
                    Xs[buf ^ 1][lk4 + i][lrow + 16] = (&px1.x)[i];
                }
                Bs[buf ^ 1][lk4 + i][lrow]      = (&pb0.x)[i];
                Bs[buf ^ 1][lk4 + i][lrow + 16] = (&pb1.x)[i];
            }
        }
        __syncthreads();
    }
}

// ---------------------------------------------------------------------------
// Single persistent fused kernel: spline + L1 + dtanh + 8 iterations.
// acc[rp][j]: f32x2 packs rows (4ty+2rp, 4ty+2rp+1) at col 2tx+j.
// ---------------------------------------------------------------------------
__global__ __launch_bounds__(TPB, 1) void fused_kernel(
    const float* __restrict__ tptr, const float* __restrict__ tobs,
    const float* __restrict__ coeffs, const float* __restrict__ dcoeffs,
    const float* __restrict__ h,  const float* __restrict__ wx,
    const float* __restrict__ wh, const float* __restrict__ wout,
    const float* __restrict__ b0, const float* __restrict__ b1,
    float* __restrict__ out) {
    __shared__ __align__(16) float As[2][BK][AST];
    __shared__ __align__(16) float Xs[2][BK][AST];
    __shared__ __align__(16) float Bs[2][BK][BST];
    __shared__ float sdr[BM][BN + 1];  // drelu tile
    __shared__ float sdt[BM][BN + 1];  // dtanh tile

    const int tid = threadIdx.x;
    const int bm = blockIdx.x * BM;   // batch rows
    const int bn = blockIdx.y * BN;   // H cols
    const int ty = tid >> 4, tx = tid & 15;
    const int r0 = 4 * ty, c0 = 2 * tx;

    unsigned gen = 0;
    if (tid == 0) gen = *((volatile unsigned*)&g_bar_gen);

    // ---- Phase 0: spline eval (bn==0 CTAs handle their bm rows) ----
    if (blockIdx.y == 0) {
        __shared__ int s_idx;
        __shared__ float s_dt;
        if (tid == 0) {
            float tv = tptr[0];
            int cnt = 0;
            for (int i = 0; i < NKNOTS; i++) cnt += (tobs[i] <= tv) ? 1 : 0;
            int idx = min(max(cnt - 1, 0), NKNOTS - 2);
            s_idx = idx;
            s_dt = tv - tobs[idx];
        }
        __syncthreads();
        const int idx = s_idx;
        const float dt = s_dt;
        for (int e = tid; e < BM * C_; e += TPB) {
            int b = bm + e / C_;
            int c = e % C_;
            size_t base = ((size_t)(b * (NKNOTS - 1) + idx)) * 4 * C_ + c;
            float a0 = coeffs[base + 0 * C_], a1 = coeffs[base + 1 * C_];
            float a2 = coeffs[base + 2 * C_], a3 = coeffs[base + 3 * C_];
            __stcg(&g_x[b * C_ + c], a0 + dt * (a1 + dt * (a2 + dt * a3)));
            a0 = dcoeffs[base + 0 * C_]; a1 = dcoeffs[base + 1 * C_];
            a2 = dcoeffs[base + 2 * C_]; a3 = dcoeffs[base + 3 * C_];
            __stcg(&g_xdot[b * C_ + c], a0 + dt * (a1 + dt * (a2 + dt * a3)));
        }
    }

    const float bc0 = b0[bn + c0], bc1 = b0[bn + c0 + 1];
    const float bz0 = b1[bn + c0], bz1 = b1[bn + c0 + 1];

    // ---- Phase L1a: acc = h@wh^T (spline latency hidden behind this) ----
    ull acc[2][2] = {}, accw[2][2] = {};
    gemm32<false, false>(h + (size_t)bm * H_, nullptr, wh + (size_t)bn * H_,
                         H_, As, Xs, Bs, acc, accw);
    gbar(gen);  // spline results visible

    // ---- Phase L1b: acc += x@wx^T, accw = xdot@wx^T ----
    gemm32<true, true>(g_x + (size_t)bm * C_, g_xdot + (size_t)bm * C_,
                       wx + (size_t)bn * C_, C_, As, Xs, Bs, acc, accw);
#pragma unroll
    for (int rp = 0; rp < 2; ++rp) {
        float2 F0 = upk2(acc[rp][0]), F1 = upk2(acc[rp][1]);
        float2 W0 = upk2(accw[rp][0]), W1 = upk2(accw[rp][1]);
        int ra = r0 + 2 * rp;
        size_t oa = (size_t)(bm + ra) * H_ + bn + c0;
        float la0 = F0.x + bc0, la1 = F1.x + bc1;   // row ra
        float lb0 = F0.y + bc0, lb1 = F1.y + bc1;   // row ra+1
        __stcg((float2*)&g_relu[oa],      make_float2(fmaxf(la0, 0.f), fmaxf(la1, 0.f)));
        __stcg((float2*)&g_relu[oa + H_], make_float2(fmaxf(lb0, 0.f), fmaxf(lb1, 0.f)));
        float da0 = 1.0f / (1.0f + expf(-la0)), da1 = 1.0f / (1.0f + expf(-la1));
        float db0 = 1.0f / (1.0f + expf(-lb0)), db1 = 1.0f / (1.0f + expf(-lb1));
        sdr[ra][c0] = da0; sdr[ra][c0 + 1] = da1;
        sdr[ra + 1][c0] = db0; sdr[ra + 1][c0 + 1] = db1;
        __stcg((float2*)&g_u[oa],      make_float2(da0 * W0.x, da1 * W1.x));
        __stcg((float2*)&g_u[oa + H_], make_float2(db0 * W0.y, db1 * W1.y));
    }
    gbar(gen);

    // ---- Phase D (dual): z = relu@wout^T, uq = u0@wout^T ----
    ull z[2][2] = {}, uq[2][2] = {};
    gemm32<true, true>(g_relu + (size_t)bm * H_, g_u + (size_t)bm * H_,
                       wout + (size_t)bn * H_, H_, As, Xs, Bs, z, uq);
    float2 hd[4];  // hdot rows r0..r0+3 at cols (c0, c0+1)
#pragma unroll
    for (int rp = 0; rp < 2; ++rp) {
        float2 Z0 = upk2(z[rp][0]), Z1 = upk2(z[rp][1]);
        float2 U0 = upk2(uq[rp][0]), U1 = upk2(uq[rp][1]);
        int ra = r0 + 2 * rp;
        size_t oa = (size_t)(bm + ra) * H_ + bn + c0;
        float ta0 = tanhf(Z0.x + bz0), ta1 = tanhf(Z1.x + bz1);
        float tb0 = tanhf(Z0.y + bz0), tb1 = tanhf(Z1.y + bz1);
        float dta0 = 1.0f - ta0 * ta0, dta1 = 1.0f - ta1 * ta1;
        float dtb0 = 1.0f - tb0 * tb0, dtb1 = 1.0f - tb1 * tb1;
        sdt[ra][c0] = dta0; sdt[ra][c0 + 1] = dta1;
        sdt[ra + 1][c0] = dtb0; sdt[ra + 1][c0 + 1] = dtb1;
        hd[2 * rp]     = make_float2(dta0 * U0.x, dta1 * U1.x);
        hd[2 * rp + 1] = make_float2(dtb0 * U0.y, dtb1 * U1.y);
        __stcg((float2*)&g_curr[oa], hd[2 * rp]);
        __stcg((float2*)&g_curr[oa + H_], hd[2 * rp + 1]);
    }
    gbar(gen);

    // ---- 8 von-Neumann iterations ----
    const size_t o = (size_t)(bm + r0) * H_ + bn + c0;
    for (int it = 0; it < KTERMS; ++it) {
        // u = drelu * (curr @ wh^T)
        ull a[2][2] = {};
        gemm32<true, false>(g_curr + (size_t)bm * H_, nullptr,
                            wh + (size_t)bn * H_, H_, As, Xs, Bs, a, uq);
#pragma unroll
        for (int rp = 0; rp < 2; ++rp) {
            float2 V0 = upk2(a[rp][0]), V1 = upk2(a[rp][1]);
            int ra = r0 + 2 * rp;
            size_t oa = o + 2 * rp * H_;
            __stcg((float2*)&g_u[oa],
                   make_float2(sdr[ra][c0] * V0.x, sdr[ra][c0 + 1] * V1.x));
            __stcg((float2*)&g_u[oa + H_],
                   make_float2(sdr[ra + 1][c0] * V0.y, sdr[ra + 1][c0 + 1] * V1.y));
        }
        gbar(gen);

        // curr = dtanh * (u @ wout^T); hdot += curr
        ull c[2][2] = {};
        gemm32<true, false>(g_u + (size_t)bm * H_, nullptr,
                            wout + (size_t)bn * H_, H_, As, Xs, Bs, c, uq);
#pragma unroll
        for (int rp = 0; rp < 2; ++rp) {
            float2 V0 = upk2(c[rp][0]), V1 = upk2(c[rp][1]);
            int ra = r0 + 2 * rp;
            size_t oa = o + 2 * rp * H_;
            float2 va = make_float2(sdt[ra][c0] * V0.x, sdt[ra][c0 + 1] * V1.x);
            float2 vb = make_float2(sdt[ra + 1][c0] * V0.y, sdt[ra + 1][c0 + 1] * V1.y);
            hd[2 * rp].x += va.x; hd[2 * rp].y += va.y;
            hd[2 * rp + 1].x += vb.x; hd[2 * rp + 1].y += vb.y;
            if (it < KTERMS - 1) {
                __stcg((float2*)&g_curr[oa], va);
                __stcg((float2*)&g_curr[oa + H_], vb);
            }
        }
        if (it < KTERMS - 1) gbar(gen);
    }

    // ---- write h_dot ----
#pragma unroll
    for (int i = 0; i < 4; ++i) {
        *(float2*)&out[o + i * H_] = hd[i];
    }
}

// ---------------------------------------------------------------------------
extern "C" void kernel_launch(void* const* d_in, const int* in_sizes, int n_in,
                              void* d_out, int out_size) {
    const float* t      = (const float*)d_in[0];
    const float* h      = (const float*)d_in[1];
    const float* coeffs = (const float*)d_in[2];
    const float* dcoeff = (const float*)d_in[3];
    const float* tobs   = (const float*)d_in[4];
    const float* wx     = (const float*)d_in[5];
    const float* wh     = (const float*)d_in[6];
    const float* wout   = (const float*)d_in[7];
    const float* b0     = (const float*)d_in[8];
    const float* b1     = (const float*)d_in[9];
    float* out = (float*)d_out;

    dim3 grid(B_ / BM, H_ / BN);  // 8 x 16 = 128 CTAs, single wave
    fused_kernel<<<grid, TPB>>>(t, tobs, coeffs, dcoeff, h, wx, wh, wout,
                                b0, b1, out);
}

// round 6
// speedup vs baseline: 1.5921x; 1.0132x over previous
#include <cuda_runtime.h>

// Problem constants
#define B_ 256
#define H_ 512
#define C_ 64
#define NKNOTS 100
#define KTERMS 8

// 32x32 CTA tile, BK=32. 512 threads = 4 K-groups x 128 threads.
// Each group: per-thread 4x2 outputs (ty=gtid>>4 rows 4ty.., tx=gtid&15 cols 2tx..),
// own SMEM tile buffers, own named barrier. Groups reduced at GEMM end.
// Grid = (256/32) x (512/32) = 8 x 16 = 128 CTAs (single wave, 1 CTA/SM).
#define BM 32
#define BN 32
#define BK 32
#define NGRP 4
#define GT 128          // threads per group
#define TPB 512
#define NCTA 128
#define AST 36          // As row stride (floats): 144B rows, 16B-aligned
#define BST 34          // Bs row stride (floats): 136B rows, 8B-aligned

typedef unsigned long long ull;

// Scratch (device globals; no allocation allowed)
__device__ float g_x[B_ * C_];
__device__ float g_xdot[B_ * C_];
__device__ float g_relu[B_ * H_];
__device__ float g_u[B_ * H_];
__device__ float g_curr[B_ * H_];

// grid-wide barrier state
__device__ unsigned g_bar_count;
__device__ unsigned g_bar_gen;

// ---------------------------------------------------------------------------
__device__ __forceinline__ void ffma2(ull& d, ull a, ull b) {
    asm("fma.rn.f32x2 %0, %1, %2, %3;" : "=l"(d) : "l"(a), "l"(b), "l"(d));
}
__device__ __forceinline__ void addf2(ull& d, ull s) {
    asm("add.rn.f32x2 %0, %1, %2;" : "=l"(d) : "l"(d), "l"(s));
}
__device__ __forceinline__ float2 upk2(ull v) {
    float2 f; asm("mov.b64 {%0, %1}, %2;" : "=f"(f.x), "=f"(f.y) : "l"(v)); return f;
}
__device__ __forceinline__ ull dup2(float b) {
    ull r; asm("mov.b64 %0, {%1, %1};" : "=l"(r) : "f"(b)); return r;
}
// per-group named barrier (ids 1..4; 0 is __syncthreads)
__device__ __forceinline__ void barg(int g) {
    asm volatile("bar.sync %0, %1;" :: "r"(g + 1), "r"(GT) : "memory");
}

// ---------------------------------------------------------------------------
// Grid-wide barrier. All 128 CTAs resident (1 CTA/SM).
// ---------------------------------------------------------------------------
__device__ __forceinline__ void gbar(unsigned& gen) {
    __syncthreads();
    if (threadIdx.x == 0) {
        __threadfence();
        unsigned old = atomicAdd(&g_bar_count, 1);
        if (old == NCTA - 1) {
            g_bar_count = 0;
            __threadfence();
            atomicAdd(&g_bar_gen, 1);
        } else {
            while (*((volatile unsigned*)&g_bar_gen) == gen) { }
        }
        __threadfence();
        gen++;
    }
    __syncthreads();
}

// ---------------------------------------------------------------------------
// Per-group NT GEMM partial: acc[rp][j] += A(32 x Kslice) * W(32 x Kslice)^T.
// Group g handles tiles t = g, g+NGRP, ... Single-buffered per-group tile,
// global prefetch one tile ahead, 2-deep LDS ring (4 warps/SMSP hide latency).
// ---------------------------------------------------------------------------
template <bool CG>
__device__ __forceinline__ void gemmK(const float* __restrict__ A,
                                      const float* __restrict__ W, int K,
                                      int g, int gtid,
                                      float (*As)[AST], float (*Bs)[BST],
                                      ull (*acc)[2]) {
    const int lrow = gtid >> 3;          // 0..15
    const int lk4  = (gtid & 7) << 2;    // 0,4,...,28
    const int ty   = gtid >> 4;          // 0..7
    const int tx   = gtid & 15;          // 0..15
    const float* asb = &As[0][4 * ty];
    const float* bsb = &Bs[0][2 * tx];
    const int NT = K / BK;

    float4 pa0, pa1, pb0, pb1;
    int t = g;
    if (t < NT) {
        const float* ap0 = A + (size_t)lrow * K + t * BK + lk4;
        const float* ap1 = A + (size_t)(lrow + 16) * K + t * BK + lk4;
        pa0 = CG ? __ldcg((const float4*)ap0) : __ldg((const float4*)ap0);
        pa1 = CG ? __ldcg((const float4*)ap1) : __ldg((const float4*)ap1);
        pb0 = __ldg((const float4*)(W + (size_t)lrow * K + t * BK + lk4));
        pb1 = __ldg((const float4*)(W + (size_t)(lrow + 16) * K + t * BK + lk4));
    }
    for (; t < NT; t += NGRP) {
#pragma unroll
        for (int i = 0; i < 4; ++i) {
            As[lk4 + i][lrow]      = (&pa0.x)[i];
            As[lk4 + i][lrow + 16] = (&pa1.x)[i];
            Bs[lk4 + i][lrow]      = (&pb0.x)[i];
            Bs[lk4 + i][lrow + 16] = (&pb1.x)[i];
        }
        barg(g);  // tile ready
        if (t + NGRP < NT) {
            int ko = (t + NGRP) * BK;
            const float* ap0 = A + (size_t)lrow * K + ko + lk4;
            const float* ap1 = A + (size_t)(lrow + 16) * K + ko + lk4;
            pa0 = CG ? __ldcg((const float4*)ap0) : __ldg((const float4*)ap0);
            pa1 = CG ? __ldcg((const float4*)ap1) : __ldg((const float4*)ap1);
            pb0 = __ldg((const float4*)(W + (size_t)lrow * K + ko + lk4));
            pb1 = __ldg((const float4*)(W + (size_t)(lrow + 16) * K + ko + lk4));
        }
        ulonglong2 a_pre[2];
        float2 b_pre[2];
        a_pre[0] = *(const ulonglong2*)(asb + 0 * AST);
        a_pre[1] = *(const ulonglong2*)(asb + 1 * AST);
        b_pre[0] = *(const float2*)(bsb + 0 * BST);
        b_pre[1] = *(const float2*)(bsb + 1 * BST);
#pragma unroll
        for (int k = 0; k < BK; ++k) {
            ulonglong2 av = a_pre[k & 1];
            float2 bv = b_pre[k & 1];
            if (k + 2 < BK) {
                a_pre[k & 1] = *(const ulonglong2*)(asb + (k + 2) * AST);
                b_pre[k & 1] = *(const float2*)(bsb + (k + 2) * BST);
            }
            ull bb0 = dup2(bv.x);
            ull bb1 = dup2(bv.y);
            ffma2(acc[0][0], av.x, bb0);
            ffma2(acc[0][1], av.x, bb1);
            ffma2(acc[1][0], av.y, bb0);
            ffma2(acc[1][1], av.y, bb1);
        }
        barg(g);  // compute done, buffer free
    }
}

// ---------------------------------------------------------------------------
// Cross-group reduction of per-thread partial accumulators into group 0.
// red overlays the sAs arena (safe: bracketed by __syncthreads).
// ---------------------------------------------------------------------------
__device__ __forceinline__ void reduce4(ull (*acc)[2], int g, int gtid,
                                        ull* red) {
    __syncthreads();
    if (g > 0) {
        ull* dst = red + ((size_t)(g - 1) * GT + gtid) * 4;
        dst[0] = acc[0][0]; dst[1] = acc[0][1];
        dst[2] = acc[1][0]; dst[3] = acc[1][1];
    }
    __syncthreads();
    if (g == 0) {
#pragma unroll
        for (int gg = 0; gg < NGRP - 1; ++gg) {
            const ull* src = red + ((size_t)gg * GT + gtid) * 4;
            addf2(acc[0][0], src[0]); addf2(acc[0][1], src[1]);
            addf2(acc[1][0], src[2]); addf2(acc[1][1], src[3]);
        }
    }
    __syncthreads();  // protect arena before next GEMM reuses it
}

// ---------------------------------------------------------------------------
// Single persistent fused kernel.
// ---------------------------------------------------------------------------
__global__ __launch_bounds__(TPB, 1) void fused_kernel(
    const float* __restrict__ tptr, const float* __restrict__ tobs,
    const float* __restrict__ coeffs, const float* __restrict__ dcoeffs,
    const float* __restrict__ h,  const float* __restrict__ wx,
    const float* __restrict__ wh, const float* __restrict__ wout,
    const float* __restrict__ b0, const float* __restrict__ b1,
    float* __restrict__ out) {
    __shared__ __align__(16) float sAs[NGRP][BK][AST];  // 18432 B (+red overlay)
    __shared__ __align__(16) float sBs[NGRP][BK][BST];  // 17408 B
    __shared__ float sdr[BM][BN + 1];                   // drelu tile
    __shared__ float sdt[BM][BN + 1];                   // dtanh tile

    const int tid  = threadIdx.x;
    const int g    = tid >> 7;        // K-group 0..3
    const int gtid = tid & (GT - 1);  // 0..127
    const int bm = blockIdx.x * BM;
    const int bn = blockIdx.y * BN;
    const int ty = gtid >> 4, tx = gtid & 15;
    const int r0 = 4 * ty, c0 = 2 * tx;

    float (*As)[AST] = sAs[g];
    float (*Bs)[BST] = sBs[g];
    ull* red = (ull*)&sAs[0][0][0];

    unsigned gen = 0;
    if (tid == 0) gen = *((volatile unsigned*)&g_bar_gen);

    // ---- Phase 0: spline eval (bn==0 CTAs cover their bm rows) ----
    if (blockIdx.y == 0) {
        __shared__ int s_idx;
        __shared__ float s_dt;
        if (tid == 0) {
            float tv = tptr[0];
            int cnt = 0;
            for (int i = 0; i < NKNOTS; i++) cnt += (tobs[i] <= tv) ? 1 : 0;
            int idx = min(max(cnt - 1, 0), NKNOTS - 2);
            s_idx = idx;
            s_dt = tv - tobs[idx];
        }
        __syncthreads();
        const int idx = s_idx;
        const float dt = s_dt;
        for (int e = tid; e < BM * C_; e += TPB) {
            int b = bm + e / C_;
            int c = e % C_;
            size_t base = ((size_t)(b * (NKNOTS - 1) + idx)) * 4 * C_ + c;
            float a0 = coeffs[base + 0 * C_], a1 = coeffs[base + 1 * C_];
            float a2 = coeffs[base + 2 * C_], a3 = coeffs[base + 3 * C_];
            __stcg(&g_x[b * C_ + c], a0 + dt * (a1 + dt * (a2 + dt * a3)));
            a0 = dcoeffs[base + 0 * C_]; a1 = dcoeffs[base + 1 * C_];
            a2 = dcoeffs[base + 2 * C_]; a3 = dcoeffs[base + 3 * C_];
            __stcg(&g_xdot[b * C_ + c], a0 + dt * (a1 + dt * (a2 + dt * a3)));
        }
    }

    const float bc0 = b0[bn + c0], bc1 = b0[bn + c0 + 1];
    const float bz0 = b1[bn + c0], bz1 = b1[bn + c0 + 1];

    // ---- L1: acc = h@wh^T + x@wx^T ; accw = xdot@wx^T ----
    ull acc[2][2] = {}, accw[2][2] = {};
    gemmK<false>(h + (size_t)bm * H_, wh + (size_t)bn * H_, H_, g, gtid, As, Bs, acc);
    gbar(gen);  // spline results visible
    gemmK<true>(g_x + (size_t)bm * C_, wx + (size_t)bn * C_, C_, g, gtid, As, Bs, acc);
    gemmK<true>(g_xdot + (size_t)bm * C_, wx + (size_t)bn * C_, C_, g, gtid, As, Bs, accw);
    reduce4(acc, g, gtid, red);
    reduce4(accw, g, gtid, red);
    if (g == 0) {
#pragma unroll
        for (int rp = 0; rp < 2; ++rp) {
            float2 F0 = upk2(acc[rp][0]), F1 = upk2(acc[rp][1]);
            float2 W0 = upk2(accw[rp][0]), W1 = upk2(accw[rp][1]);
            int ra = r0 + 2 * rp;
            size_t oa = (size_t)(bm + ra) * H_ + bn + c0;
            float la0 = F0.x + bc0, la1 = F1.x + bc1;
            float lb0 = F0.y + bc0, lb1 = F1.y + bc1;
            __stcg((float2*)&g_relu[oa],      make_float2(fmaxf(la0, 0.f), fmaxf(la1, 0.f)));
            __stcg((float2*)&g_relu[oa + H_], make_float2(fmaxf(lb0, 0.f), fmaxf(lb1, 0.f)));
            float da0 = 1.0f / (1.0f + expf(-la0)), da1 = 1.0f / (1.0f + expf(-la1));
            float db0 = 1.0f / (1.0f + expf(-lb0)), db1 = 1.0f / (1.0f + expf(-lb1));
            sdr[ra][c0] = da0; sdr[ra][c0 + 1] = da1;
            sdr[ra + 1][c0] = db0; sdr[ra + 1][c0 + 1] = db1;
            __stcg((float2*)&g_u[oa],      make_float2(da0 * W0.x, da1 * W1.x));
            __stcg((float2*)&g_u[oa + H_], make_float2(db0 * W0.y, db1 * W1.y));
        }
    }
    gbar(gen);

    // ---- z = relu@wout^T ; uq = u0@wout^T ----
    ull z[2][2] = {}, uq[2][2] = {};
    gemmK<true>(g_relu + (size_t)bm * H_, wout + (size_t)bn * H_, H_, g, gtid, As, Bs, z);
    gemmK<true>(g_u + (size_t)bm * H_, wout + (size_t)bn * H_, H_, g, gtid, As, Bs, uq);
    reduce4(z, g, gtid, red);
    reduce4(uq, g, gtid, red);
    float2 hd[4];
    if (g == 0) {
#pragma unroll
        for (int rp = 0; rp < 2; ++rp) {
            float2 Z0 = upk2(z[rp][0]), Z1 = upk2(z[rp][1]);
            float2 U0 = upk2(uq[rp][0]), U1 = upk2(uq[rp][1]);
            int ra = r0 + 2 * rp;
            size_t oa = (size_t)(bm + ra) * H_ + bn + c0;
            float ta0 = tanhf(Z0.x + bz0), ta1 = tanhf(Z1.x + bz1);
            float tb0 = tanhf(Z0.y + bz0), tb1 = tanhf(Z1.y + bz1);
            float dta0 = 1.0f - ta0 * ta0, dta1 = 1.0f - ta1 * ta1;
            float dtb0 = 1.0f - tb0 * tb0, dtb1 = 1.0f - tb1 * tb1;
            sdt[ra][c0] = dta0; sdt[ra][c0 + 1] = dta1;
            sdt[ra + 1][c0] = dtb0; sdt[ra + 1][c0 + 1] = dtb1;
            hd[2 * rp]     = make_float2(dta0 * U0.x, dta1 * U1.x);
            hd[2 * rp + 1] = make_float2(dtb0 * U0.y, dtb1 * U1.y);
            __stcg((float2*)&g_curr[oa], hd[2 * rp]);
            __stcg((float2*)&g_curr[oa + H_], hd[2 * rp + 1]);
        }
    }
    gbar(gen);

    // ---- 8 von-Neumann iterations ----
    const size_t o = (size_t)(bm + r0) * H_ + bn + c0;
    for (int it = 0; it < KTERMS; ++it) {
        // u = drelu * (curr @ wh^T)
        ull a[2][2] = {};
        gemmK<true>(g_curr + (size_t)bm * H_, wh + (size_t)bn * H_, H_, g, gtid, As, Bs, a);
        reduce4(a, g, gtid, red);
        if (g == 0) {
#pragma unroll
            for (int rp = 0; rp < 2; ++rp) {
                float2 V0 = upk2(a[rp][0]), V1 = upk2(a[rp][1]);
                int ra = r0 + 2 * rp;
                size_t oa = o + 2 * rp * H_;
                __stcg((float2*)&g_u[oa],
                       make_float2(sdr[ra][c0] * V0.x, sdr[ra][c0 + 1] * V1.x));
                __stcg((float2*)&g_u[oa + H_],
                       make_float2(sdr[ra + 1][c0] * V0.y, sdr[ra + 1][c0 + 1] * V1.y));
            }
        }
        gbar(gen);

        // curr = dtanh * (u @ wout^T); hdot += curr
        ull c[2][2] = {};
        gemmK<true>(g_u + (size_t)bm * H_, wout + (size_t)bn * H_, H_, g, gtid, As, Bs, c);
        reduce4(c, g, gtid, red);
        if (g == 0) {
#pragma unroll
            for (int rp = 0; rp < 2; ++rp) {
                float2 V0 = upk2(c[rp][0]), V1 = upk2(c[rp][1]);
                int ra = r0 + 2 * rp;
                size_t oa = o + 2 * rp * H_;
                float2 va = make_float2(sdt[ra][c0] * V0.x, sdt[ra][c0 + 1] * V1.x);
                float2 vb = make_float2(sdt[ra + 1][c0] * V0.y, sdt[ra + 1][c0 + 1] * V1.y);
                hd[2 * rp].x += va.x; hd[2 * rp].y += va.y;
                hd[2 * rp + 1].x += vb.x; hd[2 * rp + 1].y += vb.y;
                if (it < KTERMS - 1) {
                    __stcg((float2*)&g_curr[oa], va);
                    __stcg((float2*)&g_curr[oa + H_], vb);
                }
            }
        }
        if (it < KTERMS - 1) gbar(gen);
    }

    // ---- write h_dot ----
    if (g == 0) {
#pragma unroll
        for (int i = 0; i < 4; ++i) {
            *(float2*)&out[o + i * H_] = hd[i];
        }
    }
}

// ---------------------------------------------------------------------------
extern "C" void kernel_launch(void* const* d_in, const int* in_sizes, int n_in,
                              void* d_out, int out_size) {
    const float* t      = (const float*)d_in[0];
    const float* h      = (const float*)d_in[1];
    const float* coeffs = (const float*)d_in[2];
    const float* dcoeff = (const float*)d_in[3];
    const float* tobs   = (const float*)d_in[4];
    const float* wx     = (const float*)d_in[5];
    const float* wh     = (const float*)d_in[6];
    const float* wout   = (const float*)d_in[7];
    const float* b0     = (const float*)d_in[8];
    const float* b1     = (const float*)d_in[9];
    float* out = (float*)d_out;

    dim3 grid(B_ / BM, H_ / BN);  // 8 x 16 = 128 CTAs, single wave
    fused_kernel<<<grid, TPB>>>(t, tobs, coeffs, dcoeff, h, wx, wh, wout,
                                b0, b1, out);
}

// round 8
// speedup vs baseline: 2.1048x; 1.3221x over previous
#include <cuda_runtime.h>
#include <cuda_bf16.h>
#include <cstdint>

// Problem constants
#define B_ 256
#define H_ 512
#define C_ 64
#define NKNOTS 100
#define KTERMS 8

#define TPB 128
#define NCTA 128
#define GTH (NCTA * TPB)

typedef __nv_bfloat16 bf16;

// ---------------- smem layout (dynamic, byte offsets) ----------------
// W tiles: per K-chunk 32 rows x 64 bf16 SW128 tile = 4096 B; 8 chunks each.
#define SM_WHH 0u
#define SM_WHL 32768u
#define SM_WOH 65536u
#define SM_WOL 98304u
#define SM_WXH 131072u
#define SM_WXL 135168u
#define SM_AH  139264u
#define SM_AL  143360u
#define SM_TOTAL 147456u

// ---------------- global scratch (bf16 hi/lo splits) ----------------
__device__ __align__(16) bf16 g_h_hi[B_ * H_],  g_h_lo[B_ * H_];
__device__ __align__(16) bf16 g_x_hi[B_ * C_],  g_x_lo[B_ * C_];
__device__ __align__(16) bf16 g_xd_hi[B_ * C_], g_xd_lo[B_ * C_];
__device__ __align__(16) bf16 g_wh_hi[H_ * H_], g_wh_lo[H_ * H_];
__device__ __align__(16) bf16 g_wo_hi[H_ * H_], g_wo_lo[H_ * H_];
__device__ __align__(16) bf16 g_wx_hi[H_ * C_], g_wx_lo[H_ * C_];
__device__ __align__(16) bf16 g_relu_hi[B_ * H_], g_relu_lo[B_ * H_];
__device__ __align__(16) bf16 g_u_hi[B_ * H_],    g_u_lo[B_ * H_];
__device__ __align__(16) bf16 g_curr_hi[B_ * H_], g_curr_lo[B_ * H_];

__device__ unsigned g_bar_count;
__device__ unsigned g_bar_gen;

extern __shared__ char smem[];

// ---------------- helpers ----------------
__device__ __forceinline__ uint32_t smem_u32(const void* p) {
    uint32_t a;
    asm("{ .reg .u64 t; cvta.to.shared.u64 t, %1; cvt.u32.u64 %0, t; }"
        : "=r"(a) : "l"(p));
    return a;
}
// SW128 swizzle on 128B rows: byte = row*128 + u*16 -> row*128 + (u^(row&7))*16
__device__ __forceinline__ uint32_t swz(int row, int u) {
    return (uint32_t)(row * 128 + ((u ^ (row & 7)) << 4));
}

#define LDSM_X4(r, a)                                                        \
    asm volatile("ldmatrix.sync.aligned.m8n8.x4.shared.b16 {%0,%1,%2,%3}, [%4];" \
                 : "=r"((r)[0]), "=r"((r)[1]), "=r"((r)[2]), "=r"((r)[3])    \
                 : "r"(a))
#define LDSM_X2(r, a)                                                        \
    asm volatile("ldmatrix.sync.aligned.m8n8.x2.shared.b16 {%0,%1}, [%2];"   \
                 : "=r"((r)[0]), "=r"((r)[1]) : "r"(a))
#define MMA_BF16(d, a, b)                                                    \
    asm volatile("mma.sync.aligned.m16n8k16.row.col.f32.bf16.bf16.f32 "      \
                 "{%0,%1,%2,%3}, {%4,%5,%6,%7}, {%8,%9}, {%0,%1,%2,%3};"     \
                 : "+f"((d)[0]), "+f"((d)[1]), "+f"((d)[2]), "+f"((d)[3])    \
                 : "r"((a)[0]), "r"((a)[1]), "r"((a)[2]), "r"((a)[3]),       \
                   "r"((b)[0]), "r"((b)[1]))

__device__ __forceinline__ void gbar(unsigned& gen) {
    __syncthreads();
    if (threadIdx.x == 0) {
        __threadfence();
        unsigned old = atomicAdd(&g_bar_count, 1);
        if (old == NCTA - 1) {
            g_bar_count = 0;
            __threadfence();
            atomicAdd(&g_bar_gen, 1);
        } else {
            while (*((volatile unsigned*)&g_bar_gen) == gen) { }
        }
        __threadfence();
        gen++;
    }
    __syncthreads();
}

__device__ __forceinline__ void cvt_split(float v, bf16* hi, bf16* lo, int i) {
    bf16 h = __float2bfloat16(v);
    hi[i] = h;
    lo[i] = __float2bfloat16(v - __bfloat162float(h));
}

// store a pair (v0,v1) as hi/lo bf16x2 at element offset off (L2 path)
__device__ __forceinline__ void st_split_pair(bf16* hi, bf16* lo, size_t off,
                                              float v0, float v1) {
    bf16 h0 = __float2bfloat16(v0), h1 = __float2bfloat16(v1);
    unsigned uh = ((unsigned)__bfloat16_as_ushort(h1) << 16) |
                  (unsigned)__bfloat16_as_ushort(h0);
    bf16 l0 = __float2bfloat16(v0 - __bfloat162float(h0));
    bf16 l1 = __float2bfloat16(v1 - __bfloat162float(h1));
    unsigned ul = ((unsigned)__bfloat16_as_ushort(l1) << 16) |
                  (unsigned)__bfloat16_as_ushort(l0);
    __stcg((unsigned*)(hi + off), uh);
    __stcg((unsigned*)(lo + off), ul);
}

// ---------------------------------------------------------------------------
// NT GEMM partial: acc{0,1} (2 m16 tiles) += A(32 x 64*nch) * Wtile^T via
// 3-term bf16-split HMMA. W tiles resident in smem (whi/wlo, 4096B/chunk).
// A streamed per chunk into SM_AH/SM_AL with one-chunk LDG prefetch.
// ---------------------------------------------------------------------------
template <bool CG>
__device__ __forceinline__ void gemmT(const bf16* __restrict__ Ahi,
                                      const bf16* __restrict__ Alo,
                                      int strideA, int bm, uint32_t sb,
                                      uint32_t whi, uint32_t wlo, int nch,
                                      float acc0[4], float acc1[4]) {
    const int tid = threadIdx.x;
    const int w = tid >> 5, l = tid & 31;
    // fill mapping: thread -> row fr (0..31), 16B units fu, fu+1
    const int fr = tid >> 2;
    const int fu = (tid & 3) * 2;
    const uint32_t d_h0 = SM_AH + swz(fr, fu);
    const uint32_t d_h1 = SM_AH + swz(fr, fu + 1);
    const uint32_t d_l0 = SM_AL + swz(fr, fu);
    const uint32_t d_l1 = SM_AL + swz(fr, fu + 1);
    const bf16* gh = Ahi + (size_t)(bm + fr) * strideA + fu * 8;
    const bf16* gl = Alo + (size_t)(bm + fr) * strideA + fu * 8;
    // ldmatrix lane mapping
    const int lrow = l & 15, kh = l >> 4;          // A: row-in-16, k-half
    const int brow = w * 8 + (l & 7), bsel = (l >> 3) & 1;  // B

    uint4 ph0 = CG ? __ldcg((const uint4*)gh) : __ldg((const uint4*)gh);
    uint4 ph1 = CG ? __ldcg((const uint4*)(gh + 8)) : __ldg((const uint4*)(gh + 8));
    uint4 pl0 = CG ? __ldcg((const uint4*)gl) : __ldg((const uint4*)gl);
    uint4 pl1 = CG ? __ldcg((const uint4*)(gl + 8)) : __ldg((const uint4*)(gl + 8));

    for (int c = 0; c < nch; ++c) {
        __syncthreads();  // A buffer free
        *(uint4*)(smem + d_h0) = ph0;
        *(uint4*)(smem + d_h1) = ph1;
        *(uint4*)(smem + d_l0) = pl0;
        *(uint4*)(smem + d_l1) = pl1;
        __syncthreads();  // A tile visible
        if (c + 1 < nch) {
            gh += 64; gl += 64;
            ph0 = CG ? __ldcg((const uint4*)gh) : __ldg((const uint4*)gh);
            ph1 = CG ? __ldcg((const uint4*)(gh + 8)) : __ldg((const uint4*)(gh + 8));
            pl0 = CG ? __ldcg((const uint4*)gl) : __ldg((const uint4*)gl);
            pl1 = CG ? __ldcg((const uint4*)(gl + 8)) : __ldg((const uint4*)(gl + 8));
        }
        const uint32_t whc = sb + whi + c * 4096;
        const uint32_t wlc = sb + wlo + c * 4096;
#pragma unroll
        for (int ks = 0; ks < 4; ++ks) {
            const int ua = ks * 2 + kh;
            const uint32_t am0 = sb + SM_AH + swz(lrow, ua);
            const uint32_t am1 = sb + SM_AH + swz(16 + lrow, ua);
            const int ub = ks * 2 + bsel;
            const uint32_t boff = swz(brow, ub);
            uint32_t ah0[4], ah1[4], al0[4], al1[4], bh[2], bl[2];
            LDSM_X4(ah0, am0);
            LDSM_X4(ah1, am1);
            LDSM_X4(al0, am0 + 4096u);   // SM_AL = SM_AH + 4096
            LDSM_X4(al1, am1 + 4096u);
            LDSM_X2(bh, whc + boff);
            LDSM_X2(bl, wlc + boff);
            MMA_BF16(acc0, ah0, bh);
            MMA_BF16(acc1, ah1, bh);
            MMA_BF16(acc0, al0, bh);
            MMA_BF16(acc1, al1, bh);
            MMA_BF16(acc0, ah0, bl);
            MMA_BF16(acc1, ah1, bl);
        }
    }
}

// load one resident W slice (rows bn..bn+31, K=512 as 8 SW128 chunk tiles)
__device__ __forceinline__ void load_w(const bf16* __restrict__ src,
                                       uint32_t soff, int bn, int K) {
    const int tid = threadIdx.x;
    const int nu = (K / 64) * 32 * 8;  // chunk tiles * rows * units
    for (int e = tid; e < nu; e += TPB) {
        int kc = e >> 8;
        int r = (e >> 3) & 31;
        int j = e & 7;
        uint4 v = __ldg((const uint4*)(src + (size_t)(bn + r) * K + kc * 64 + j * 8));
        *(uint4*)(smem + soff + kc * 4096 + swz(r, j)) = v;
    }
}

// ---------------------------------------------------------------------------
__global__ void __launch_bounds__(TPB, 1) cde_kernel(
    const float* __restrict__ tptr, const float* __restrict__ tobs,
    const float* __restrict__ coeffs, const float* __restrict__ dcoeffs,
    const float* __restrict__ h, const float* __restrict__ wx,
    const float* __restrict__ wh, const float* __restrict__ wout,
    const float* __restrict__ b0, const float* __restrict__ b1,
    float* __restrict__ out) {
    const int tid = threadIdx.x;
    const int w = tid >> 5, l = tid & 31;
    const int gid = l >> 2, tig = l & 3;
    const int bm = blockIdx.x * 32;
    const int bn = blockIdx.y * 32;
    const uint32_t sb = smem_u32(smem);

    unsigned gen = 0;
    if (tid == 0) gen = *((volatile unsigned*)&g_bar_gen);

    // ---- Phase -1: spline + fp32 -> bf16 hi/lo splits (grid-flat) ----
    {
        const int gt = (blockIdx.y * gridDim.x + blockIdx.x) * TPB + tid;
        float tv = tptr[0];
        int idx = 0;
        for (int i = 0; i < NKNOTS; i++) idx += (tobs[i] <= tv) ? 1 : 0;
        idx = min(max(idx - 1, 0), NKNOTS - 2);
        const float dt = tv - tobs[idx];
        for (int i = gt; i < B_ * C_; i += GTH) {
            int b = i / C_, c = i % C_;
            size_t base = ((size_t)(b * (NKNOTS - 1) + idx)) * 4 * C_ + c;
            float v = coeffs[base] + dt * (coeffs[base + C_] +
                      dt * (coeffs[base + 2 * C_] + dt * coeffs[base + 3 * C_]));
            cvt_split(v, g_x_hi, g_x_lo, i);
            v = dcoeffs[base] + dt * (dcoeffs[base + C_] +
                dt * (dcoeffs[base + 2 * C_] + dt * dcoeffs[base + 3 * C_]));
            cvt_split(v, g_xd_hi, g_xd_lo, i);
        }
        for (int i = gt; i < B_ * H_; i += GTH) cvt_split(h[i], g_h_hi, g_h_lo, i);
        for (int i = gt; i < H_ * H_; i += GTH) cvt_split(wh[i], g_wh_hi, g_wh_lo, i);
        for (int i = gt; i < H_ * H_; i += GTH) cvt_split(wout[i], g_wo_hi, g_wo_lo, i);
        for (int i = gt; i < H_ * C_; i += GTH) cvt_split(wx[i], g_wx_hi, g_wx_lo, i);
    }
    gbar(gen);

    // ---- resident W tiles for this CTA's 32 cols ----
    load_w(g_wh_hi, SM_WHH, bn, H_);
    load_w(g_wh_lo, SM_WHL, bn, H_);
    load_w(g_wo_hi, SM_WOH, bn, H_);
    load_w(g_wo_lo, SM_WOL, bn, H_);
    load_w(g_wx_hi, SM_WXH, bn, C_);
    load_w(g_wx_lo, SM_WXL, bn, C_);
    // (gemmT's leading __syncthreads orders these STS before ldmatrix reads)

    // fragment-position constants: 4 (row, col-pair) groups per lane
    const int col0 = bn + w * 8 + tig * 2;
    const float bc0 = b0[col0], bc1 = b0[col0 + 1];
    const float bz0 = b1[col0], bz1 = b1[col0 + 1];
    int rw[4];
#pragma unroll
    for (int p = 0; p < 4; ++p) rw[p] = (p >> 1) * 16 + (p & 1) * 8 + gid;

    float sdr[8], sdt[8], hd[8];

    // ---- L1: acc = h@wh^T + x@wx^T ; aw = xdot@wx^T ----
    {
        float a0[4] = {}, a1[4] = {}, w0[4] = {}, w1[4] = {};
        gemmT<false>(g_h_hi, g_h_lo, H_, bm, sb, SM_WHH, SM_WHL, 8, a0, a1);
        gemmT<true>(g_x_hi, g_x_lo, C_, bm, sb, SM_WXH, SM_WXL, 1, a0, a1);
        gemmT<true>(g_xd_hi, g_xd_lo, C_, bm, sb, SM_WXH, SM_WXL, 1, w0, w1);
#pragma unroll
        for (int p = 0; p < 4; ++p) {
            const float* ac = (p >> 1) ? a1 : a0;
            const float* wc = (p >> 1) ? w1 : w0;
            float v0 = ac[(p & 1) * 2 + 0] + bc0;
            float v1 = ac[(p & 1) * 2 + 1] + bc1;
            size_t off = (size_t)(bm + rw[p]) * H_ + col0;
            st_split_pair(g_relu_hi, g_relu_lo, off, fmaxf(v0, 0.f), fmaxf(v1, 0.f));
            float d0 = 1.0f / (1.0f + expf(-v0));
            float d1 = 1.0f / (1.0f + expf(-v1));
            sdr[p * 2] = d0;
            sdr[p * 2 + 1] = d1;
            st_split_pair(g_u_hi, g_u_lo, off,
                          d0 * wc[(p & 1) * 2 + 0], d1 * wc[(p & 1) * 2 + 1]);
        }
    }
    gbar(gen);

    // ---- Z: z = relu@wout^T ; uq = u0@wout^T ----
    {
        float z0[4] = {}, z1[4] = {}, q0[4] = {}, q1[4] = {};
        gemmT<true>(g_relu_hi, g_relu_lo, H_, bm, sb, SM_WOH, SM_WOL, 8, z0, z1);
        gemmT<true>(g_u_hi, g_u_lo, H_, bm, sb, SM_WOH, SM_WOL, 8, q0, q1);
#pragma unroll
        for (int p = 0; p < 4; ++p) {
            const float* zc = (p >> 1) ? z1 : z0;
            const float* qc = (p >> 1) ? q1 : q0;
            float t0 = tanhf(zc[(p & 1) * 2 + 0] + bz0);
            float t1 = tanhf(zc[(p & 1) * 2 + 1] + bz1);
            float d0 = 1.0f - t0 * t0, d1 = 1.0f - t1 * t1;
            sdt[p * 2] = d0;
            sdt[p * 2 + 1] = d1;
            float v0 = d0 * qc[(p & 1) * 2 + 0];
            float v1 = d1 * qc[(p & 1) * 2 + 1];
            hd[p * 2] = v0;
            hd[p * 2 + 1] = v1;
            size_t off = (size_t)(bm + rw[p]) * H_ + col0;
            st_split_pair(g_curr_hi, g_curr_lo, off, v0, v1);
        }
    }
    gbar(gen);

    // ---- 8 von-Neumann iterations ----
    for (int it = 0; it < KTERMS; ++it) {
        {   // u = drelu * (curr @ wh^T)
            float a0[4] = {}, a1[4] = {};
            gemmT<true>(g_curr_hi, g_curr_lo, H_, bm, sb, SM_WHH, SM_WHL, 8, a0, a1);
#pragma unroll
            for (int p = 0; p < 4; ++p) {
                const float* ac = (p >> 1) ? a1 : a0;
                size_t off = (size_t)(bm + rw[p]) * H_ + col0;
                st_split_pair(g_u_hi, g_u_lo, off,
                              sdr[p * 2] * ac[(p & 1) * 2 + 0],
                              sdr[p * 2 + 1] * ac[(p & 1) * 2 + 1]);
            }
        }
        gbar(gen);
        {   // curr' = dtanh * (u @ wout^T); hdot += curr'
            float c0[4] = {}, c1[4] = {};
            gemmT<true>(g_u_hi, g_u_lo, H_, bm, sb, SM_WOH, SM_WOL, 8, c0, c1);
#pragma unroll
            for (int p = 0; p < 4; ++p) {
                const float* cc = (p >> 1) ? c1 : c0;
                float v0 = sdt[p * 2] * cc[(p & 1) * 2 + 0];
                float v1 = sdt[p * 2 + 1] * cc[(p & 1) * 2 + 1];
                hd[p * 2] += v0;
                hd[p * 2 + 1] += v1;
                if (it < KTERMS - 1) {
                    size_t off = (size_t)(bm + rw[p]) * H_ + col0;
                    st_split_pair(g_curr_hi, g_curr_lo, off, v0, v1);
                }
            }
            if (it < KTERMS - 1) gbar(gen);
        }
    }

    // ---- write h_dot (fp32) ----
#pragma unroll
    for (int p = 0; p < 4; ++p) {
        size_t off = (size_t)(bm + rw[p]) * H_ + col0;
        *(float2*)(out + off) = make_float2(hd[p * 2], hd[p * 2 + 1]);
    }
}

// ---------------------------------------------------------------------------
extern "C" void kernel_launch(void* const* d_in, const int* in_sizes, int n_in,
                              void* d_out, int out_size) {
    const float* t      = (const float*)d_in[0];
    const float* h      = (const float*)d_in[1];
    const float* coeffs = (const float*)d_in[2];
    const float* dcoeff = (const float*)d_in[3];
    const float* tobs   = (const float*)d_in[4];
    const float* wx     = (const float*)d_in[5];
    const float* wh     = (const float*)d_in[6];
    const float* wout   = (const float*)d_in[7];
    const float* b0     = (const float*)d_in[8];
    const float* b1     = (const float*)d_in[9];
    float* out = (float*)d_out;

    cudaFuncSetAttribute(cde_kernel, cudaFuncAttributeMaxDynamicSharedMemorySize,
                         SM_TOTAL);
    dim3 grid(B_ / 32, H_ / 32);  // 8 x 16 = 128 CTAs, single wave
    cde_kernel<<<grid, TPB, SM_TOTAL>>>(t, tobs, coeffs, dcoeff, h, wx, wh,
                                        wout, b0, b1, out);
}

// round 9
// speedup vs baseline: 2.3800x; 1.1307x over previous
#include <cuda_runtime.h>
#include <cuda_bf16.h>
#include <cstdint>

// Problem constants
#define B_ 256
#define H_ 512
#define C_ 64
#define NKNOTS 100
#define KTERMS 8

#define TPB 256
#define NCTA 128
#define GTH (NCTA * TPB)

typedef __nv_bfloat16 bf16;

// ---------------- smem layout (dynamic, byte offsets) ----------------
// W tiles: per K-chunk 32 rows x 64 bf16 SW128 tile = 4096 B; 8 chunks each.
#define SM_WHH 0u
#define SM_WHL 32768u
#define SM_WOH 65536u
#define SM_WOL 98304u
#define SM_WXH 131072u
#define SM_WXL 135168u
#define SM_A   139264u     // A buffers: buf b at +b*8192 (hi 4096, lo 4096)
#define SM_TOTAL 155648u

// ---------------- global scratch (bf16 hi/lo splits) ----------------
__device__ __align__(16) bf16 g_h_hi[B_ * H_],  g_h_lo[B_ * H_];
__device__ __align__(16) bf16 g_x_hi[B_ * C_],  g_x_lo[B_ * C_];
__device__ __align__(16) bf16 g_xd_hi[B_ * C_], g_xd_lo[B_ * C_];
__device__ __align__(16) bf16 g_wh_hi[H_ * H_], g_wh_lo[H_ * H_];
__device__ __align__(16) bf16 g_wo_hi[H_ * H_], g_wo_lo[H_ * H_];
__device__ __align__(16) bf16 g_wx_hi[H_ * C_], g_wx_lo[H_ * C_];
__device__ __align__(16) bf16 g_relu_hi[B_ * H_], g_relu_lo[B_ * H_];
__device__ __align__(16) bf16 g_u_hi[B_ * H_],    g_u_lo[B_ * H_];
__device__ __align__(16) bf16 g_curr_hi[B_ * H_], g_curr_lo[B_ * H_];

__device__ unsigned g_bar_count;
__device__ unsigned g_bar_gen;

extern __shared__ char smem[];

// ---------------- helpers ----------------
__device__ __forceinline__ uint32_t smem_u32(const void* p) {
    uint32_t a;
    asm("{ .reg .u64 t; cvta.to.shared.u64 t, %1; cvt.u32.u64 %0, t; }"
        : "=r"(a) : "l"(p));
    return a;
}
// SW128 swizzle on 128B rows: byte = row*128 + u*16 -> row*128 + (u^(row&7))*16
__device__ __forceinline__ uint32_t swz(int row, int u) {
    return (uint32_t)(row * 128 + ((u ^ (row & 7)) << 4));
}

#define LDSM_X4(r, a)                                                        \
    asm volatile("ldmatrix.sync.aligned.m8n8.x4.shared.b16 {%0,%1,%2,%3}, [%4];" \
                 : "=r"((r)[0]), "=r"((r)[1]), "=r"((r)[2]), "=r"((r)[3])    \
                 : "r"(a))
#define LDSM_X2(r, a)                                                        \
    asm volatile("ldmatrix.sync.aligned.m8n8.x2.shared.b16 {%0,%1}, [%2];"   \
                 : "=r"((r)[0]), "=r"((r)[1]) : "r"(a))
#define MMA_BF16(d, a, b)                                                    \
    asm volatile("mma.sync.aligned.m16n8k16.row.col.f32.bf16.bf16.f32 "      \
                 "{%0,%1,%2,%3}, {%4,%5,%6,%7}, {%8,%9}, {%0,%1,%2,%3};"     \
                 : "+f"((d)[0]), "+f"((d)[1]), "+f"((d)[2]), "+f"((d)[3])    \
                 : "r"((a)[0]), "r"((a)[1]), "r"((a)[2]), "r"((a)[3]),       \
                   "r"((b)[0]), "r"((b)[1]))

__device__ __forceinline__ void gbar(unsigned& gen) {
    __syncthreads();
    if (threadIdx.x == 0) {
        __threadfence();
        unsigned old = atomicAdd(&g_bar_count, 1);
        if (old == NCTA - 1) {
            g_bar_count = 0;
            __threadfence();
            atomicAdd(&g_bar_gen, 1);
        } else {
            while (*((volatile unsigned*)&g_bar_gen) == gen) { }
        }
        __threadfence();
        gen++;
    }
    __syncthreads();
}

__device__ __forceinline__ void cvt_split(float v, bf16* hi, bf16* lo, int i) {
    bf16 h = __float2bfloat16(v);
    hi[i] = h;
    lo[i] = __float2bfloat16(v - __bfloat162float(h));
}

// store a pair (v0,v1) as hi/lo bf16x2 at element offset off (L2 path)
__device__ __forceinline__ void st_split_pair(bf16* hi, bf16* lo, size_t off,
                                              float v0, float v1) {
    bf16 h0 = __float2bfloat16(v0), h1 = __float2bfloat16(v1);
    unsigned uh = ((unsigned)__bfloat16_as_ushort(h1) << 16) |
                  (unsigned)__bfloat16_as_ushort(h0);
    bf16 l0 = __float2bfloat16(v0 - __bfloat162float(h0));
    bf16 l1 = __float2bfloat16(v1 - __bfloat162float(h1));
    unsigned ul = ((unsigned)__bfloat16_as_ushort(l1) << 16) |
                  (unsigned)__bfloat16_as_ushort(l0);
    __stcg((unsigned*)(hi + off), uh);
    __stcg((unsigned*)(lo + off), ul);
}

// ---------------------------------------------------------------------------
// NT GEMM partial: acc (one m16n8 tile per warp) += A(32 x 64*nch) * W^T.
// 8 warps: warp w -> m-tile (w>>2), n-group (w&3). 3-term bf16-split HMMA.
// W tiles resident in smem; A double-buffered, one sync/chunk, B hoisted.
// ---------------------------------------------------------------------------
template <bool CG>
__device__ __forceinline__ void gemmT(const bf16* __restrict__ Ahi,
                                      const bf16* __restrict__ Alo,
                                      int strideA, int bm, uint32_t sb,
                                      uint32_t whi, uint32_t wlo, int nch,
                                      float acc[4]) {
    const int tid = threadIdx.x;
    const int w = tid >> 5, l = tid & 31;
    const int mt = w >> 2, ng = w & 3;
    // fill mapping: 256 threads cover 32 rows x 8 units (hi + lo each)
    const int fr = tid >> 3, fu = tid & 7;
    const uint32_t d_a = swz(fr, fu);
    const bf16* gh = Ahi + (size_t)(bm + fr) * strideA + fu * 8;
    const bf16* gl = Alo + (size_t)(bm + fr) * strideA + fu * 8;
    // ldmatrix lane mapping
    const int lrow = mt * 16 + (l & 15), kh = l >> 4;       // A
    const int brow = ng * 8 + (l & 7), bsel = (l >> 3) & 1; // B

    uint4 ph = CG ? __ldcg((const uint4*)gh) : __ldg((const uint4*)gh);
    uint4 pl = CG ? __ldcg((const uint4*)gl) : __ldg((const uint4*)gl);

    __syncthreads();  // protect A buffers from previous GEMM's in-flight reads
    for (int c = 0; c < nch; ++c) {
        const uint32_t ab = SM_A + (uint32_t)(c & 1) * 8192u;
        *(uint4*)(smem + ab + d_a) = ph;
        *(uint4*)(smem + ab + 4096u + d_a) = pl;
        __syncthreads();  // tile c visible (and buf c&1 free from chunk c-2)
        if (c + 1 < nch) {
            gh += 64; gl += 64;
            ph = CG ? __ldcg((const uint4*)gh) : __ldg((const uint4*)gh);
            pl = CG ? __ldcg((const uint4*)gl) : __ldg((const uint4*)gl);
        }
        // hoist all B fragments for this chunk (independent of A ldsm)
        const uint32_t whc = sb + whi + c * 4096u;
        const uint32_t wlc = sb + wlo + c * 4096u;
        uint32_t bh[4][2], bl[4][2];
#pragma unroll
        for (int ks = 0; ks < 4; ++ks) {
            const uint32_t boff = swz(brow, ks * 2 + bsel);
            LDSM_X2(bh[ks], whc + boff);
            LDSM_X2(bl[ks], wlc + boff);
        }
#pragma unroll
        for (int ks = 0; ks < 4; ++ks) {
            const uint32_t am = sb + ab + swz(lrow, ks * 2 + kh);
            uint32_t ah[4], al[4];
            LDSM_X4(ah, am);
            LDSM_X4(al, am + 4096u);
            MMA_BF16(acc, ah, bh[ks]);
            MMA_BF16(acc, al, bh[ks]);
            MMA_BF16(acc, ah, bl[ks]);
        }
    }
}

// load one resident W slice (rows bn..bn+31, K as SW128 chunk tiles)
__device__ __forceinline__ void load_w(const bf16* __restrict__ src,
                                       uint32_t soff, int bn, int K) {
    const int tid = threadIdx.x;
    const int nu = (K / 64) * 32 * 8;
    for (int e = tid; e < nu; e += TPB) {
        int kc = e >> 8;
        int r = (e >> 3) & 31;
        int j = e & 7;
        uint4 v = __ldg((const uint4*)(src + (size_t)(bn + r) * K + kc * 64 + j * 8));
        *(uint4*)(smem + soff + kc * 4096 + swz(r, j)) = v;
    }
}

// ---------------------------------------------------------------------------
__global__ void __launch_bounds__(TPB, 1) cde_kernel(
    const float* __restrict__ tptr, const float* __restrict__ tobs,
    const float* __restrict__ coeffs, const float* __restrict__ dcoeffs,
    const float* __restrict__ h, const float* __restrict__ wx,
    const float* __restrict__ wh, const float* __restrict__ wout,
    const float* __restrict__ b0, const float* __restrict__ b1,
    float* __restrict__ out) {
    const int tid = threadIdx.x;
    const int w = tid >> 5, l = tid & 31;
    const int mt = w >> 2, ng = w & 3;
    const int gid = l >> 2;
    const int bm = blockIdx.x * 32;
    const int bn = blockIdx.y * 32;
    const uint32_t sb = smem_u32(smem);

    unsigned gen = 0;
    if (tid == 0) gen = *((volatile unsigned*)&g_bar_gen);

    // ---- Phase -1: spline + fp32 -> bf16 hi/lo splits (grid-flat) ----
    {
        const int gt = (blockIdx.y * gridDim.x + blockIdx.x) * TPB + tid;
        float tv = tptr[0];
        int idx = 0;
        for (int i = 0; i < NKNOTS; i++) idx += (tobs[i] <= tv) ? 1 : 0;
        idx = min(max(idx - 1, 0), NKNOTS - 2);
        const float dt = tv - tobs[idx];
        for (int i = gt; i < B_ * C_; i += GTH) {
            int b = i / C_, c = i % C_;
            size_t base = ((size_t)(b * (NKNOTS - 1) + idx)) * 4 * C_ + c;
            float v = coeffs[base] + dt * (coeffs[base + C_] +
                      dt * (coeffs[base + 2 * C_] + dt * coeffs[base + 3 * C_]));
            cvt_split(v, g_x_hi, g_x_lo, i);
            v = dcoeffs[base] + dt * (dcoeffs[base + C_] +
                dt * (dcoeffs[base + 2 * C_] + dt * dcoeffs[base + 3 * C_]));
            cvt_split(v, g_xd_hi, g_xd_lo, i);
        }
        for (int i = gt; i < B_ * H_; i += GTH) cvt_split(h[i], g_h_hi, g_h_lo, i);
        for (int i = gt; i < H_ * H_; i += GTH) cvt_split(wh[i], g_wh_hi, g_wh_lo, i);
        for (int i = gt; i < H_ * H_; i += GTH) cvt_split(wout[i], g_wo_hi, g_wo_lo, i);
        for (int i = gt; i < H_ * C_; i += GTH) cvt_split(wx[i], g_wx_hi, g_wx_lo, i);
    }
    gbar(gen);

    // ---- resident W tiles for this CTA's 32 cols ----
    load_w(g_wh_hi, SM_WHH, bn, H_);
    load_w(g_wh_lo, SM_WHL, bn, H_);
    load_w(g_wo_hi, SM_WOH, bn, H_);
    load_w(g_wo_lo, SM_WOL, bn, H_);
    load_w(g_wx_hi, SM_WXH, bn, C_);
    load_w(g_wx_lo, SM_WXL, bn, C_);
    // (gemmT's leading __syncthreads orders these STS before ldmatrix reads)

    // fragment position: warp owns m16 rows mt*16.., cols ng*8 + (l&3)*2 +{0,1}
    const int col0 = bn + ng * 8 + (l & 3) * 2;
    const float bc0 = b0[col0], bc1 = b0[col0 + 1];
    const float bz0 = b1[col0], bz1 = b1[col0 + 1];
    int rw[2];
    rw[0] = mt * 16 + gid;
    rw[1] = mt * 16 + 8 + gid;

    float sdr[4], sdt[4], hd[4];

    // ---- L1: acc = h@wh^T + x@wx^T ; aw = xdot@wx^T ----
    {
        float a[4] = {}, aw[4] = {};
        gemmT<false>(g_h_hi, g_h_lo, H_, bm, sb, SM_WHH, SM_WHL, 8, a);
        gemmT<true>(g_x_hi, g_x_lo, C_, bm, sb, SM_WXH, SM_WXL, 1, a);
        gemmT<true>(g_xd_hi, g_xd_lo, C_, bm, sb, SM_WXH, SM_WXL, 1, aw);
#pragma unroll
        for (int p = 0; p < 2; ++p) {
            float v0 = a[p * 2 + 0] + bc0;
            float v1 = a[p * 2 + 1] + bc1;
            size_t off = (size_t)(bm + rw[p]) * H_ + col0;
            st_split_pair(g_relu_hi, g_relu_lo, off, fmaxf(v0, 0.f), fmaxf(v1, 0.f));
            float d0 = 1.0f / (1.0f + expf(-v0));
            float d1 = 1.0f / (1.0f + expf(-v1));
            sdr[p * 2] = d0;
            sdr[p * 2 + 1] = d1;
            st_split_pair(g_u_hi, g_u_lo, off, d0 * aw[p * 2], d1 * aw[p * 2 + 1]);
        }
    }
    gbar(gen);

    // ---- Z: z = relu@wout^T ; uq = u0@wout^T ----
    {
        float z[4] = {}, q[4] = {};
        gemmT<true>(g_relu_hi, g_relu_lo, H_, bm, sb, SM_WOH, SM_WOL, 8, z);
        gemmT<true>(g_u_hi, g_u_lo, H_, bm, sb, SM_WOH, SM_WOL, 8, q);
#pragma unroll
        for (int p = 0; p < 2; ++p) {
            float t0 = tanhf(z[p * 2 + 0] + bz0);
            float t1 = tanhf(z[p * 2 + 1] + bz1);
            float d0 = 1.0f - t0 * t0, d1 = 1.0f - t1 * t1;
            sdt[p * 2] = d0;
            sdt[p * 2 + 1] = d1;
            float v0 = d0 * q[p * 2], v1 = d1 * q[p * 2 + 1];
            hd[p * 2] = v0;
            hd[p * 2 + 1] = v1;
            size_t off = (size_t)(bm + rw[p]) * H_ + col0;
            st_split_pair(g_curr_hi, g_curr_lo, off, v0, v1);
        }
    }
    gbar(gen);

    // ---- 8 von-Neumann iterations ----
    for (int it = 0; it < KTERMS; ++it) {
        {   // u = drelu * (curr @ wh^T)
            float a[4] = {};
            gemmT<true>(g_curr_hi, g_curr_lo, H_, bm, sb, SM_WHH, SM_WHL, 8, a);
#pragma unroll
            for (int p = 0; p < 2; ++p) {
                size_t off = (size_t)(bm + rw[p]) * H_ + col0;
                st_split_pair(g_u_hi, g_u_lo, off,
                              sdr[p * 2] * a[p * 2], sdr[p * 2 + 1] * a[p * 2 + 1]);
            }
        }
        gbar(gen);
        {   // curr' = dtanh * (u @ wout^T); hdot += curr'
            float c[4] = {};
            gemmT<true>(g_u_hi, g_u_lo, H_, bm, sb, SM_WOH, SM_WOL, 8, c);
#pragma unroll
            for (int p = 0; p < 2; ++p) {
                float v0 = sdt[p * 2] * c[p * 2];
                float v1 = sdt[p * 2 + 1] * c[p * 2 + 1];
                hd[p * 2] += v0;
                hd[p * 2 + 1] += v1;
                if (it < KTERMS - 1) {
                    size_t off = (size_t)(bm + rw[p]) * H_ + col0;
                    st_split_pair(g_curr_hi, g_curr_lo, off, v0, v1);
                }
            }
            if (it < KTERMS - 1) gbar(gen);
        }
    }

    // ---- write h_dot (fp32) ----
#pragma unroll
    for (int p = 0; p < 2; ++p) {
        size_t off = (size_t)(bm + rw[p]) * H_ + col0;
        *(float2*)(out + off) = make_float2(hd[p * 2], hd[p * 2 + 1]);
    }
}

// ---------------------------------------------------------------------------
extern "C" void kernel_launch(void* const* d_in, const int* in_sizes, int n_in,
                              void* d_out, int out_size) {
    const float* t      = (const float*)d_in[0];
    const float* h      = (const float*)d_in[1];
    const float* coeffs = (const float*)d_in[2];
    const float* dcoeff = (const float*)d_in[3];
    const float* tobs   = (const float*)d_in[4];
    const float* wx     = (const float*)d_in[5];
    const float* wh     = (const float*)d_in[6];
    const float* wout   = (const float*)d_in[7];
    const float* b0     = (const float*)d_in[8];
    const float* b1     = (const float*)d_in[9];
    float* out = (float*)d_out;

    cudaFuncSetAttribute(cde_kernel, cudaFuncAttributeMaxDynamicSharedMemorySize,
                         SM_TOTAL);
    dim3 grid(B_ / 32, H_ / 32);  // 8 x 16 = 128 CTAs, single wave
    cde_kernel<<<grid, TPB, SM_TOTAL>>>(t, tobs, coeffs, dcoeff, h, wx, wh,
                                        wout, b0, b1, out);
}

// round 10
// speedup vs baseline: 2.6867x; 1.1288x over previous
#include <cuda_runtime.h>
#include <cuda_bf16.h>
#include <cstdint>

// Problem constants
#define B_ 256
#define H_ 512
#define C_ 64
#define NKNOTS 100
#define KTERMS 8

#define TPB 256
#define NCTA 128
#define GTH (NCTA * TPB)

typedef __nv_bfloat16 bf16;

// ---------------- smem layout (dynamic, byte offsets) ----------------
// W tiles: per K-chunk 32 rows x 64 bf16 SW128 tile = 4096 B; 8 chunks each.
// A: full 32 x 512 staged per GEMM: hi chunks at SM_A + c*4096,
//    lo chunks at SM_A + 32768 + c*4096.
#define SM_WHH 0u
#define SM_WHL 32768u
#define SM_WOH 65536u
#define SM_WOL 98304u
#define SM_WXH 131072u
#define SM_WXL 135168u
#define SM_A   139264u
#define SM_ALO 172032u     // SM_A + 32768
#define SM_TOTAL 204800u

// ---------------- global scratch (bf16 hi/lo splits) ----------------
__device__ __align__(16) bf16 g_h_hi[B_ * H_],  g_h_lo[B_ * H_];
__device__ __align__(16) bf16 g_x_hi[B_ * C_],  g_x_lo[B_ * C_];
__device__ __align__(16) bf16 g_xd_hi[B_ * C_], g_xd_lo[B_ * C_];
__device__ __align__(16) bf16 g_wh_hi[H_ * H_], g_wh_lo[H_ * H_];
__device__ __align__(16) bf16 g_wo_hi[H_ * H_], g_wo_lo[H_ * H_];
__device__ __align__(16) bf16 g_wx_hi[H_ * C_], g_wx_lo[H_ * C_];
__device__ __align__(16) bf16 g_relu_hi[B_ * H_], g_relu_lo[B_ * H_];
__device__ __align__(16) bf16 g_u_hi[B_ * H_],    g_u_lo[B_ * H_];
__device__ __align__(16) bf16 g_curr_hi[B_ * H_], g_curr_lo[B_ * H_];

__device__ unsigned g_bar_count;
__device__ unsigned g_bar_gen;

extern __shared__ char smem[];

// ---------------- helpers ----------------
__device__ __forceinline__ uint32_t smem_u32(const void* p) {
    uint32_t a;
    asm("{ .reg .u64 t; cvta.to.shared.u64 t, %1; cvt.u32.u64 %0, t; }"
        : "=r"(a) : "l"(p));
    return a;
}
// SW128 swizzle on 128B rows: byte = row*128 + u*16 -> row*128 + (u^(row&7))*16
__device__ __forceinline__ uint32_t swz(int row, int u) {
    return (uint32_t)(row * 128 + ((u ^ (row & 7)) << 4));
}

#define LDSM_X4(r, a)                                                        \
    asm volatile("ldmatrix.sync.aligned.m8n8.x4.shared.b16 {%0,%1,%2,%3}, [%4];" \
                 : "=r"((r)[0]), "=r"((r)[1]), "=r"((r)[2]), "=r"((r)[3])    \
                 : "r"(a))
#define LDSM_X2(r, a)                                                        \
    asm volatile("ldmatrix.sync.aligned.m8n8.x2.shared.b16 {%0,%1}, [%2];"   \
                 : "=r"((r)[0]), "=r"((r)[1]) : "r"(a))
#define MMA_BF16(d, a, b)                                                    \
    asm volatile("mma.sync.aligned.m16n8k16.row.col.f32.bf16.bf16.f32 "      \
                 "{%0,%1,%2,%3}, {%4,%5,%6,%7}, {%8,%9}, {%0,%1,%2,%3};"     \
                 : "+f"((d)[0]), "+f"((d)[1]), "+f"((d)[2]), "+f"((d)[3])    \
                 : "r"((a)[0]), "r"((a)[1]), "r"((a)[2]), "r"((a)[3]),       \
                   "r"((b)[0]), "r"((b)[1]))

__device__ __forceinline__ void gbar(unsigned& gen) {
    __syncthreads();
    if (threadIdx.x == 0) {
        __threadfence();
        unsigned old = atomicAdd(&g_bar_count, 1);
        if (old == NCTA - 1) {
            g_bar_count = 0;
            __threadfence();
            atomicAdd(&g_bar_gen, 1);
        } else {
            while (*((volatile unsigned*)&g_bar_gen) == gen) { }
        }
        __threadfence();
        gen++;
    }
    __syncthreads();
}

__device__ __forceinline__ void cvt_split(float v, bf16* hi, bf16* lo, int i) {
    bf16 h = __float2bfloat16(v);
    hi[i] = h;
    lo[i] = __float2bfloat16(v - __bfloat162float(h));
}

// store a pair (v0,v1) as hi/lo bf16x2 at element offset off (L2 path)
__device__ __forceinline__ void st_split_pair(bf16* hi, bf16* lo, size_t off,
                                              float v0, float v1) {
    bf16 h0 = __float2bfloat16(v0), h1 = __float2bfloat16(v1);
    unsigned uh = ((unsigned)__bfloat16_as_ushort(h1) << 16) |
                  (unsigned)__bfloat16_as_ushort(h0);
    bf16 l0 = __float2bfloat16(v0 - __bfloat162float(h0));
    bf16 l1 = __float2bfloat16(v1 - __bfloat162float(h1));
    unsigned ul = ((unsigned)__bfloat16_as_ushort(l1) << 16) |
                  (unsigned)__bfloat16_as_ushort(l0);
    __stcg((unsigned*)(hi + off), uh);
    __stcg((unsigned*)(lo + off), ul);
}

// ---------------------------------------------------------------------------
// NT GEMM partial: acc (one m16n8 tile per warp) += A(32 x 64*NCH) * W^T.
// 8 warps: warp w -> m-tile (w>>2), n-group (w&3). 3-term bf16-split HMMA.
// One-shot A staging: all NCH chunks' LDGs issued back-to-back (MLP=2*NCH),
// one STS pass, one sync, then all chunks computed with no further syncs.
// ---------------------------------------------------------------------------
template <bool CG, int NCH>
__device__ __forceinline__ void gemmT(const bf16* __restrict__ Ahi,
                                      const bf16* __restrict__ Alo,
                                      int strideA, int bm, uint32_t sb,
                                      uint32_t whi, uint32_t wlo,
                                      float acc[4]) {
    const int tid = threadIdx.x;
    const int w = tid >> 5, l = tid & 31;
    const int mt = w >> 2, ng = w & 3;
    // fill mapping: 256 threads cover 32 rows x 8 x 16B units per chunk
    const int fr = tid >> 3, fu = tid & 7;
    const uint32_t d_a = swz(fr, fu);
    const bf16* gh = Ahi + (size_t)(bm + fr) * strideA + fu * 8;
    const bf16* gl = Alo + (size_t)(bm + fr) * strideA + fu * 8;
    // ldmatrix lane mapping
    const int lrow = mt * 16 + (l & 15), kh = l >> 4;       // A
    const int brow = ng * 8 + (l & 7), bsel = (l >> 3) & 1; // B

    uint4 vh[NCH], vl[NCH];
#pragma unroll
    for (int c = 0; c < NCH; ++c) {
        vh[c] = CG ? __ldcg((const uint4*)(gh + c * 64)) : __ldg((const uint4*)(gh + c * 64));
        vl[c] = CG ? __ldcg((const uint4*)(gl + c * 64)) : __ldg((const uint4*)(gl + c * 64));
    }
    __syncthreads();  // previous GEMM's reads of SM_A complete
#pragma unroll
    for (int c = 0; c < NCH; ++c) {
        *(uint4*)(smem + SM_A + c * 4096u + d_a) = vh[c];
        *(uint4*)(smem + SM_ALO + c * 4096u + d_a) = vl[c];
    }
    __syncthreads();  // full A visible

#pragma unroll
    for (int c = 0; c < NCH; ++c) {
        const uint32_t whc = sb + whi + c * 4096u;
        const uint32_t wlc = sb + wlo + c * 4096u;
        const uint32_t ac = sb + SM_A + c * 4096u;
        uint32_t bh[4][2], bl[4][2];
#pragma unroll
        for (int ks = 0; ks < 4; ++ks) {
            const uint32_t boff = swz(brow, ks * 2 + bsel);
            LDSM_X2(bh[ks], whc + boff);
            LDSM_X2(bl[ks], wlc + boff);
        }
#pragma unroll
        for (int ks = 0; ks < 4; ++ks) {
            const uint32_t am = ac + swz(lrow, ks * 2 + kh);
            uint32_t ah[4], al[4];
            LDSM_X4(ah, am);
            LDSM_X4(al, am + 32768u);   // SM_ALO - SM_A
            MMA_BF16(acc, ah, bh[ks]);
            MMA_BF16(acc, al, bh[ks]);
            MMA_BF16(acc, ah, bl[ks]);
        }
    }
}

// load one resident W slice (rows bn..bn+31, K as SW128 chunk tiles)
__device__ __forceinline__ void load_w(const bf16* __restrict__ src,
                                       uint32_t soff, int bn, int K) {
    const int tid = threadIdx.x;
    const int nu = (K / 64) * 32 * 8;
    for (int e = tid; e < nu; e += TPB) {
        int kc = e >> 8;
        int r = (e >> 3) & 31;
        int j = e & 7;
        uint4 v = __ldg((const uint4*)(src + (size_t)(bn + r) * K + kc * 64 + j * 8));
        *(uint4*)(smem + soff + kc * 4096 + swz(r, j)) = v;
    }
}

// ---------------------------------------------------------------------------
__global__ void __launch_bounds__(TPB, 1) cde_kernel(
    const float* __restrict__ tptr, const float* __restrict__ tobs,
    const float* __restrict__ coeffs, const float* __restrict__ dcoeffs,
    const float* __restrict__ h, const float* __restrict__ wx,
    const float* __restrict__ wh, const float* __restrict__ wout,
    const float* __restrict__ b0, const float* __restrict__ b1,
    float* __restrict__ out) {
    const int tid = threadIdx.x;
    const int w = tid >> 5, l = tid & 31;
    const int mt = w >> 2, ng = w & 3;
    const int gid = l >> 2;
    const int bm = blockIdx.x * 32;
    const int bn = blockIdx.y * 32;
    const uint32_t sb = smem_u32(smem);

    unsigned gen = 0;
    if (tid == 0) gen = *((volatile unsigned*)&g_bar_gen);

    // ---- Phase -1: spline + fp32 -> bf16 hi/lo splits (grid-flat) ----
    {
        const int gt = (blockIdx.y * gridDim.x + blockIdx.x) * TPB + tid;
        float tv = tptr[0];
        int idx = 0;
        for (int i = 0; i < NKNOTS; i++) idx += (tobs[i] <= tv) ? 1 : 0;
        idx = min(max(idx - 1, 0), NKNOTS - 2);
        const float dt = tv - tobs[idx];
        for (int i = gt; i < B_ * C_; i += GTH) {
            int b = i / C_, c = i % C_;
            size_t base = ((size_t)(b * (NKNOTS - 1) + idx)) * 4 * C_ + c;
            float v = coeffs[base] + dt * (coeffs[base + C_] +
                      dt * (coeffs[base + 2 * C_] + dt * coeffs[base + 3 * C_]));
            cvt_split(v, g_x_hi, g_x_lo, i);
            v = dcoeffs[base] + dt * (dcoeffs[base + C_] +
                dt * (dcoeffs[base + 2 * C_] + dt * dcoeffs[base + 3 * C_]));
            cvt_split(v, g_xd_hi, g_xd_lo, i);
        }
        for (int i = gt; i < B_ * H_; i += GTH) cvt_split(h[i], g_h_hi, g_h_lo, i);
        for (int i = gt; i < H_ * H_; i += GTH) cvt_split(wh[i], g_wh_hi, g_wh_lo, i);
        for (int i = gt; i < H_ * H_; i += GTH) cvt_split(wout[i], g_wo_hi, g_wo_lo, i);
        for (int i = gt; i < H_ * C_; i += GTH) cvt_split(wx[i], g_wx_hi, g_wx_lo, i);
    }
    gbar(gen);

    // ---- resident W tiles for this CTA's 32 cols ----
    load_w(g_wh_hi, SM_WHH, bn, H_);
    load_w(g_wh_lo, SM_WHL, bn, H_);
    load_w(g_wo_hi, SM_WOH, bn, H_);
    load_w(g_wo_lo, SM_WOL, bn, H_);
    load_w(g_wx_hi, SM_WXH, bn, C_);
    load_w(g_wx_lo, SM_WXL, bn, C_);
    // (gemmT's leading __syncthreads orders these STS before ldmatrix reads)

    // fragment position: warp owns m16 rows mt*16.., cols ng*8 + (l&3)*2 +{0,1}
    const int col0 = bn + ng * 8 + (l & 3) * 2;
    const float bc0 = b0[col0], bc1 = b0[col0 + 1];
    const float bz0 = b1[col0], bz1 = b1[col0 + 1];
    int rw[2];
    rw[0] = mt * 16 + gid;
    rw[1] = mt * 16 + 8 + gid;

    float sdr[4], sdt[4], hd[4];

    // ---- L1: acc = h@wh^T + x@wx^T ; aw = xdot@wx^T ----
    {
        float a[4] = {}, aw[4] = {};
        gemmT<false, 8>(g_h_hi, g_h_lo, H_, bm, sb, SM_WHH, SM_WHL, a);
        gemmT<true, 1>(g_x_hi, g_x_lo, C_, bm, sb, SM_WXH, SM_WXL, a);
        gemmT<true, 1>(g_xd_hi, g_xd_lo, C_, bm, sb, SM_WXH, SM_WXL, aw);
#pragma unroll
        for (int p = 0; p < 2; ++p) {
            float v0 = a[p * 2 + 0] + bc0;
            float v1 = a[p * 2 + 1] + bc1;
            size_t off = (size_t)(bm + rw[p]) * H_ + col0;
            st_split_pair(g_relu_hi, g_relu_lo, off, fmaxf(v0, 0.f), fmaxf(v1, 0.f));
            float d0 = 1.0f / (1.0f + expf(-v0));
            float d1 = 1.0f / (1.0f + expf(-v1));
            sdr[p * 2] = d0;
            sdr[p * 2 + 1] = d1;
            st_split_pair(g_u_hi, g_u_lo, off, d0 * aw[p * 2], d1 * aw[p * 2 + 1]);
        }
    }
    gbar(gen);

    // ---- Z: z = relu@wout^T ; uq = u0@wout^T ----
    {
        float z[4] = {}, q[4] = {};
        gemmT<true, 8>(g_relu_hi, g_relu_lo, H_, bm, sb, SM_WOH, SM_WOL, z);
        gemmT<true, 8>(g_u_hi, g_u_lo, H_, bm, sb, SM_WOH, SM_WOL, q);
#pragma unroll
        for (int p = 0; p < 2; ++p) {
            float t0 = tanhf(z[p * 2 + 0] + bz0);
            float t1 = tanhf(z[p * 2 + 1] + bz1);
            float d0 = 1.0f - t0 * t0, d1 = 1.0f - t1 * t1;
            sdt[p * 2] = d0;
            sdt[p * 2 + 1] = d1;
            float v0 = d0 * q[p * 2], v1 = d1 * q[p * 2 + 1];
            hd[p * 2] = v0;
            hd[p * 2 + 1] = v1;
            size_t off = (size_t)(bm + rw[p]) * H_ + col0;
            st_split_pair(g_curr_hi, g_curr_lo, off, v0, v1);
        }
    }
    gbar(gen);

    // ---- 8 von-Neumann iterations ----
    for (int it = 0; it < KTERMS; ++it) {
        {   // u = drelu * (curr @ wh^T)
            float a[4] = {};
            gemmT<true, 8>(g_curr_hi, g_curr_lo, H_, bm, sb, SM_WHH, SM_WHL, a);
#pragma unroll
            for (int p = 0; p < 2; ++p) {
                size_t off = (size_t)(bm + rw[p]) * H_ + col0;
                st_split_pair(g_u_hi, g_u_lo, off,
                              sdr[p * 2] * a[p * 2], sdr[p * 2 + 1] * a[p * 2 + 1]);
            }
        }
        gbar(gen);
        {   // curr' = dtanh * (u @ wout^T); hdot += curr'
            float c[4] = {};
            gemmT<true, 8>(g_u_hi, g_u_lo, H_, bm, sb, SM_WOH, SM_WOL, c);
#pragma unroll
            for (int p = 0; p < 2; ++p) {
                float v0 = sdt[p * 2] * c[p * 2];
                float v1 = sdt[p * 2 + 1] * c[p * 2 + 1];
                hd[p * 2] += v0;
                hd[p * 2 + 1] += v1;
                if (it < KTERMS - 1) {
                    size_t off = (size_t)(bm + rw[p]) * H_ + col0;
                    st_split_pair(g_curr_hi, g_curr_lo, off, v0, v1);
                }
            }
            if (it < KTERMS - 1) gbar(gen);
        }
    }

    // ---- write h_dot (fp32) ----
#pragma unroll
    for (int p = 0; p < 2; ++p) {
        size_t off = (size_t)(bm + rw[p]) * H_ + col0;
        *(float2*)(out + off) = make_float2(hd[p * 2], hd[p * 2 + 1]);
    }
}

// ---------------------------------------------------------------------------
extern "C" void kernel_launch(void* const* d_in, const int* in_sizes, int n_in,
                              void* d_out, int out_size) {
    const float* t      = (const float*)d_in[0];
    const float* h      = (const float*)d_in[1];
    const float* coeffs = (const float*)d_in[2];
    const float* dcoeff = (const float*)d_in[3];
    const float* tobs   = (const float*)d_in[4];
    const float* wx     = (const float*)d_in[5];
    const float* wh     = (const float*)d_in[6];
    const float* wout   = (const float*)d_in[7];
    const float* b0     = (const float*)d_in[8];
    const float* b1     = (const float*)d_in[9];
    float* out = (float*)d_out;

    cudaFuncSetAttribute(cde_kernel, cudaFuncAttributeMaxDynamicSharedMemorySize,
                         SM_TOTAL);
    dim3 grid(B_ / 32, H_ / 32);  // 8 x 16 = 128 CTAs, single wave
    cde_kernel<<<grid, TPB, SM_TOTAL>>>(t, tobs, coeffs, dcoeff, h, wx, wh,
                                        wout, b0, b1, out);
}

// round 11
// speedup vs baseline: 3.1018x; 1.1545x over previous
#include <cuda_runtime.h>
#include <cuda_bf16.h>
#include <cstdint>

// Problem constants
#define B_ 256
#define H_ 512
#define C_ 64
#define NKNOTS 100
#define KTERMS 8

#define TPB 256
#define NCTA 128
#define GTH (NCTA * TPB)

typedef __nv_bfloat16 bf16;

// ---------------- smem layout (dynamic, byte offsets) ----------------
#define SM_WHH 0u
#define SM_WHL 32768u
#define SM_WOH 65536u
#define SM_WOL 98304u
#define SM_WXH 131072u
#define SM_WXL 135168u
#define SM_A   139264u
#define SM_ALO 172032u     // SM_A + 32768
#define SM_TOTAL 204800u

// ---------------- global scratch (bf16 hi/lo splits) ----------------
__device__ __align__(16) bf16 g_h_hi[B_ * H_],  g_h_lo[B_ * H_];
__device__ __align__(16) bf16 g_x_hi[B_ * C_],  g_x_lo[B_ * C_];
__device__ __align__(16) bf16 g_xd_hi[B_ * C_], g_xd_lo[B_ * C_];
__device__ __align__(16) bf16 g_wh_hi[H_ * H_], g_wh_lo[H_ * H_];
__device__ __align__(16) bf16 g_wo_hi[H_ * H_], g_wo_lo[H_ * H_];
__device__ __align__(16) bf16 g_wx_hi[H_ * C_], g_wx_lo[H_ * C_];
__device__ __align__(16) bf16 g_relu_hi[B_ * H_], g_relu_lo[B_ * H_];
__device__ __align__(16) bf16 g_u_hi[B_ * H_],    g_u_lo[B_ * H_];
__device__ __align__(16) bf16 g_curr_hi[B_ * H_], g_curr_lo[B_ * H_];

__device__ unsigned g_bar_count;
__device__ unsigned g_bar_gen;

extern __shared__ char smem[];

// ---------------- helpers ----------------
__device__ __forceinline__ uint32_t smem_u32(const void* p) {
    uint32_t a;
    asm("{ .reg .u64 t; cvta.to.shared.u64 t, %1; cvt.u32.u64 %0, t; }"
        : "=r"(a) : "l"(p));
    return a;
}
// SW128 swizzle on 128B rows
__device__ __forceinline__ uint32_t swz(int row, int u) {
    return (uint32_t)(row * 128 + ((u ^ (row & 7)) << 4));
}

#define CP_ASYNC16(sa, gp)                                                   \
    asm volatile("cp.async.cg.shared.global [%0], [%1], 16;"                 \
                 :: "r"((uint32_t)(sa)), "l"(gp))
#define CP_COMMIT() asm volatile("cp.async.commit_group;" ::: "memory")
#define CP_WAIT0()  asm volatile("cp.async.wait_group 0;" ::: "memory")

#define LDSM_X4(r, a)                                                        \
    asm volatile("ldmatrix.sync.aligned.m8n8.x4.shared.b16 {%0,%1,%2,%3}, [%4];" \
                 : "=r"((r)[0]), "=r"((r)[1]), "=r"((r)[2]), "=r"((r)[3])    \
                 : "r"(a))
#define LDSM_X2(r, a)                                                        \
    asm volatile("ldmatrix.sync.aligned.m8n8.x2.shared.b16 {%0,%1}, [%2];"   \
                 : "=r"((r)[0]), "=r"((r)[1]) : "r"(a))
#define MMA_BF16(d, a, b)                                                    \
    asm volatile("mma.sync.aligned.m16n8k16.row.col.f32.bf16.bf16.f32 "      \
                 "{%0,%1,%2,%3}, {%4,%5,%6,%7}, {%8,%9}, {%0,%1,%2,%3};"     \
                 : "+f"((d)[0]), "+f"((d)[1]), "+f"((d)[2]), "+f"((d)[3])    \
                 : "r"((a)[0]), "r"((a)[1]), "r"((a)[2]), "r"((a)[3]),       \
                   "r"((b)[0]), "r"((b)[1]))

__device__ __forceinline__ void gbar(unsigned& gen) {
    __syncthreads();
    if (threadIdx.x == 0) {
        __threadfence();
        unsigned old = atomicAdd(&g_bar_count, 1);
        if (old == NCTA - 1) {
            g_bar_count = 0;
            __threadfence();
            atomicAdd(&g_bar_gen, 1);
        } else {
            while (*((volatile unsigned*)&g_bar_gen) == gen) { }
        }
        __threadfence();
        gen++;
    }
    __syncthreads();
}

__device__ __forceinline__ void cvt_split(float v, bf16* hi, bf16* lo, int i) {
    bf16 h = __float2bfloat16(v);
    hi[i] = h;
    lo[i] = __float2bfloat16(v - __bfloat162float(h));
}

// store a pair (v0,v1) as hi/lo bf16x2 at element offset off (L2 path)
__device__ __forceinline__ void st_split_pair(bf16* hi, bf16* lo, size_t off,
                                              float v0, float v1) {
    bf16 h0 = __float2bfloat16(v0), h1 = __float2bfloat16(v1);
    unsigned uh = ((unsigned)__bfloat16_as_ushort(h1) << 16) |
                  (unsigned)__bfloat16_as_ushort(h0);
    bf16 l0 = __float2bfloat16(v0 - __bfloat162float(h0));
    bf16 l1 = __float2bfloat16(v1 - __bfloat162float(h1));
    unsigned ul = ((unsigned)__bfloat16_as_ushort(l1) << 16) |
                  (unsigned)__bfloat16_as_ushort(l0);
    __stcg((unsigned*)(hi + off), uh);
    __stcg((unsigned*)(lo + off), ul);
}

// ---------------------------------------------------------------------------
// NT GEMM partial with TERM-SPLIT accumulators:
//   acc[0] += Ahi*Whi, acc[1] += Alo*Whi, acc[2] += Ahi*Wlo
// (three independent HMMA chains; combined at the epilogue).
// A staged one-shot per GEMM via cp.async.cg (register-free, L2-coherent).
// 8 warps: warp w -> m-tile (w>>2), n-group (w&3).
// ---------------------------------------------------------------------------
template <int NCH>
__device__ __forceinline__ void gemmT(const bf16* __restrict__ Ahi,
                                      const bf16* __restrict__ Alo,
                                      int strideA, int bm, uint32_t sb,
                                      uint32_t whi, uint32_t wlo,
                                      float (&acc)[3][4]) {
    const int tid = threadIdx.x;
    const int w = tid >> 5, l = tid & 31;
    const int mt = w >> 2, ng = w & 3;
    // fill mapping: 256 threads cover 32 rows x 8 x 16B units per chunk
    const int fr = tid >> 3, fu = tid & 7;
    const uint32_t d_a = swz(fr, fu);
    const bf16* gh = Ahi + (size_t)(bm + fr) * strideA + fu * 8;
    const bf16* gl = Alo + (size_t)(bm + fr) * strideA + fu * 8;
    // ldmatrix lane mapping
    const int lrow = mt * 16 + (l & 15), kh = l >> 4;       // A
    const int brow = ng * 8 + (l & 7), bsel = (l >> 3) & 1; // B

    __syncthreads();  // previous GEMM's reads of SM_A complete
#pragma unroll
    for (int c = 0; c < NCH; ++c) {
        CP_ASYNC16(sb + SM_A + c * 4096u + d_a, gh + c * 64);
        CP_ASYNC16(sb + SM_ALO + c * 4096u + d_a, gl + c * 64);
    }
    CP_COMMIT();
    CP_WAIT0();
    __syncthreads();  // full A visible to all warps

#pragma unroll
    for (int c = 0; c < NCH; ++c) {
        const uint32_t whc = sb + whi + c * 4096u;
        const uint32_t wlc = sb + wlo + c * 4096u;
        const uint32_t ac = sb + SM_A + c * 4096u;
        uint32_t bh[4][2], bl[4][2];
#pragma unroll
        for (int ks = 0; ks < 4; ++ks) {
            const uint32_t boff = swz(brow, ks * 2 + bsel);
            LDSM_X2(bh[ks], whc + boff);
            LDSM_X2(bl[ks], wlc + boff);
        }
#pragma unroll
        for (int ks = 0; ks < 4; ++ks) {
            const uint32_t am = ac + swz(lrow, ks * 2 + kh);
            uint32_t ah[4], al[4];
            LDSM_X4(ah, am);
            LDSM_X4(al, am + 32768u);   // SM_ALO - SM_A
            MMA_BF16(acc[0], ah, bh[ks]);
            MMA_BF16(acc[1], al, bh[ks]);
            MMA_BF16(acc[2], ah, bl[ks]);
        }
    }
}

__device__ __forceinline__ float fin(const float (&a)[3][4], int i) {
    return (a[0][i] + a[1][i]) + a[2][i];
}

// load one resident W slice (rows bn..bn+31, K as SW128 chunk tiles), cp.async
__device__ __forceinline__ void load_w(const bf16* __restrict__ src,
                                       uint32_t sb, uint32_t soff, int bn, int K) {
    const int tid = threadIdx.x;
    const int nu = (K / 64) * 32 * 8;
    for (int e = tid; e < nu; e += TPB) {
        int kc = e >> 8;
        int r = (e >> 3) & 31;
        int j = e & 7;
        CP_ASYNC16(sb + soff + kc * 4096 + swz(r, j),
                   src + (size_t)(bn + r) * K + kc * 64 + j * 8);
    }
}

// ---------------------------------------------------------------------------
__global__ void __launch_bounds__(TPB, 1) cde_kernel(
    const float* __restrict__ tptr, const float* __restrict__ tobs,
    const float* __restrict__ coeffs, const float* __restrict__ dcoeffs,
    const float* __restrict__ h, const float* __restrict__ wx,
    const float* __restrict__ wh, const float* __restrict__ wout,
    const float* __restrict__ b0, const float* __restrict__ b1,
    float* __restrict__ out) {
    const int tid = threadIdx.x;
    const int w = tid >> 5, l = tid & 31;
    const int mt = w >> 2, ng = w & 3;
    const int gid = l >> 2;
    const int bm = blockIdx.x * 32;
    const int bn = blockIdx.y * 32;
    const uint32_t sb = smem_u32(smem);

    unsigned gen = 0;
    if (tid == 0) gen = *((volatile unsigned*)&g_bar_gen);

    // ---- Phase -1: spline + fp32 -> bf16 hi/lo splits (grid-flat) ----
    {
        const int gt = (blockIdx.y * gridDim.x + blockIdx.x) * TPB + tid;
        float tv = tptr[0];
        int idx = 0;
        for (int i = 0; i < NKNOTS; i++) idx += (tobs[i] <= tv) ? 1 : 0;
        idx = min(max(idx - 1, 0), NKNOTS - 2);
        const float dt = tv - tobs[idx];
        for (int i = gt; i < B_ * C_; i += GTH) {
            int b = i / C_, c = i % C_;
            size_t base = ((size_t)(b * (NKNOTS - 1) + idx)) * 4 * C_ + c;
            float v = coeffs[base] + dt * (coeffs[base + C_] +
                      dt * (coeffs[base + 2 * C_] + dt * coeffs[base + 3 * C_]));
            cvt_split(v, g_x_hi, g_x_lo, i);
            v = dcoeffs[base] + dt * (dcoeffs[base + C_] +
                dt * (dcoeffs[base + 2 * C_] + dt * dcoeffs[base + 3 * C_]));
            cvt_split(v, g_xd_hi, g_xd_lo, i);
        }
        for (int i = gt; i < B_ * H_; i += GTH) cvt_split(h[i], g_h_hi, g_h_lo, i);
        for (int i = gt; i < H_ * H_; i += GTH) cvt_split(wh[i], g_wh_hi, g_wh_lo, i);
        for (int i = gt; i < H_ * H_; i += GTH) cvt_split(wout[i], g_wo_hi, g_wo_lo, i);
        for (int i = gt; i < H_ * C_; i += GTH) cvt_split(wx[i], g_wx_hi, g_wx_lo, i);
    }
    gbar(gen);

    // ---- resident W tiles for this CTA's 32 cols (cp.async; completion
    //      guaranteed by the first gemmT's CP_WAIT0 before any ldsm) ----
    load_w(g_wh_hi, sb, SM_WHH, bn, H_);
    load_w(g_wh_lo, sb, SM_WHL, bn, H_);
    load_w(g_wo_hi, sb, SM_WOH, bn, H_);
    load_w(g_wo_lo, sb, SM_WOL, bn, H_);
    load_w(g_wx_hi, sb, SM_WXH, bn, C_);
    load_w(g_wx_lo, sb, SM_WXL, bn, C_);
    CP_COMMIT();

    // fragment position: warp owns m16 rows mt*16.., cols ng*8 + (l&3)*2 +{0,1}
    const int col0 = bn + ng * 8 + (l & 3) * 2;
    const float bc0 = b0[col0], bc1 = b0[col0 + 1];
    const float bz0 = b1[col0], bz1 = b1[col0 + 1];
    int rw[2];
    rw[0] = mt * 16 + gid;
    rw[1] = mt * 16 + 8 + gid;

    float sdr[4], sdt[4], hd[4];

    // ---- L1: acc = h@wh^T + x@wx^T ; aw = xdot@wx^T ----
    {
        float a[3][4] = {}, aw[3][4] = {};
        gemmT<8>(g_h_hi, g_h_lo, H_, bm, sb, SM_WHH, SM_WHL, a);
        gemmT<1>(g_x_hi, g_x_lo, C_, bm, sb, SM_WXH, SM_WXL, a);
        gemmT<1>(g_xd_hi, g_xd_lo, C_, bm, sb, SM_WXH, SM_WXL, aw);
#pragma unroll
        for (int p = 0; p < 2; ++p) {
            float v0 = fin(a, p * 2 + 0) + bc0;
            float v1 = fin(a, p * 2 + 1) + bc1;
            size_t off = (size_t)(bm + rw[p]) * H_ + col0;
            st_split_pair(g_relu_hi, g_relu_lo, off, fmaxf(v0, 0.f), fmaxf(v1, 0.f));
            float d0 = 1.0f / (1.0f + expf(-v0));
            float d1 = 1.0f / (1.0f + expf(-v1));
            sdr[p * 2] = d0;
            sdr[p * 2 + 1] = d1;
            st_split_pair(g_u_hi, g_u_lo, off,
                          d0 * fin(aw, p * 2), d1 * fin(aw, p * 2 + 1));
        }
    }
    gbar(gen);

    // ---- Z: z = relu@wout^T ; uq = u0@wout^T ----
    {
        float z[3][4] = {}, q[3][4] = {};
        gemmT<8>(g_relu_hi, g_relu_lo, H_, bm, sb, SM_WOH, SM_WOL, z);
        gemmT<8>(g_u_hi, g_u_lo, H_, bm, sb, SM_WOH, SM_WOL, q);
#pragma unroll
        for (int p = 0; p < 2; ++p) {
            float t0 = tanhf(fin(z, p * 2 + 0) + bz0);
            float t1 = tanhf(fin(z, p * 2 + 1) + bz1);
            float d0 = 1.0f - t0 * t0, d1 = 1.0f - t1 * t1;
            sdt[p * 2] = d0;
            sdt[p * 2 + 1] = d1;
            float v0 = d0 * fin(q, p * 2), v1 = d1 * fin(q, p * 2 + 1);
            hd[p * 2] = v0;
            hd[p * 2 + 1] = v1;
            size_t off = (size_t)(bm + rw[p]) * H_ + col0;
            st_split_pair(g_curr_hi, g_curr_lo, off, v0, v1);
        }
    }
    gbar(gen);

    // ---- 8 von-Neumann iterations ----
    for (int it = 0; it < KTERMS; ++it) {
        {   // u = drelu * (curr @ wh^T)
            float a[3][4] = {};
            gemmT<8>(g_curr_hi, g_curr_lo, H_, bm, sb, SM_WHH, SM_WHL, a);
#pragma unroll
            for (int p = 0; p < 2; ++p) {
                size_t off = (size_t)(bm + rw[p]) * H_ + col0;
                st_split_pair(g_u_hi, g_u_lo, off,
                              sdr[p * 2] * fin(a, p * 2),
                              sdr[p * 2 + 1] * fin(a, p * 2 + 1));
            }
        }
        gbar(gen);
        {   // curr' = dtanh * (u @ wout^T); hdot += curr'
            float c[3][4] = {};
            gemmT<8>(g_u_hi, g_u_lo, H_, bm, sb, SM_WOH, SM_WOL, c);
#pragma unroll
            for (int p = 0; p < 2; ++p) {
                float v0 = sdt[p * 2] * fin(c, p * 2);
                float v1 = sdt[p * 2 + 1] * fin(c, p * 2 + 1);
                hd[p * 2] += v0;
                hd[p * 2 + 1] += v1;
                if (it < KTERMS - 1) {
                    size_t off = (size_t)(bm + rw[p]) * H_ + col0;
                    st_split_pair(g_curr_hi, g_curr_lo, off, v0, v1);
                }
            }
            if (it < KTERMS - 1) gbar(gen);
        }
    }

    // ---- write h_dot (fp32) ----
#pragma unroll
    for (int p = 0; p < 2; ++p) {
        size_t off = (size_t)(bm + rw[p]) * H_ + col0;
        *(float2*)(out + off) = make_float2(hd[p * 2], hd[p * 2 + 1]);
    }
}

// ---------------------------------------------------------------------------
extern "C" void kernel_launch(void* const* d_in, const int* in_sizes, int n_in,
                              void* d_out, int out_size) {
    const float* t      = (const float*)d_in[0];
    const float* h      = (const float*)d_in[1];
    const float* coeffs = (const float*)d_in[2];
    const float* dcoeff = (const float*)d_in[3];
    const float* tobs   = (const float*)d_in[4];
    const float* wx     = (const float*)d_in[5];
    const float* wh     = (const float*)d_in[6];
    const float* wout   = (const float*)d_in[7];
    const float* b0     = (const float*)d_in[8];
    const float* b1     = (const float*)d_in[9];
    float* out = (float*)d_out;

    cudaFuncSetAttribute(cde_kernel, cudaFuncAttributeMaxDynamicSharedMemorySize,
                         SM_TOTAL);
    dim3 grid(B_ / 32, H_ / 32);  // 8 x 16 = 128 CTAs, single wave
    cde_kernel<<<grid, TPB, SM_TOTAL>>>(t, tobs, coeffs, dcoeff, h, wx, wh,
                                        wout, b0, b1, out);
}

// round 12
// speedup vs baseline: 3.2409x; 1.0449x over previous
#include <cuda_runtime.h>
#include <cuda_bf16.h>
#include <cstdint>

// Problem constants
#define B_ 256
#define H_ 512
#define C_ 64
#define NKNOTS 100
#define KTERMS 8

#define TPB 256
#define NCTA 128
#define NROWG 8            // row groups (blockIdx.x)
#define RG_CTAS 16         // CTAs per row group (gridDim.y)
#define GTH (NCTA * TPB)

typedef __nv_bfloat16 bf16;

// ---------------- smem layout (dynamic, byte offsets) ----------------
#define SM_WHH 0u
#define SM_WHL 32768u
#define SM_WOH 65536u
#define SM_WOL 98304u
#define SM_WXH 131072u
#define SM_WXL 135168u
#define SM_A   139264u
#define SM_ALO 172032u     // SM_A + 32768
#define SM_TOTAL 204800u

// ---------------- global scratch (bf16 hi/lo splits) ----------------
__device__ __align__(16) bf16 g_h_hi[B_ * H_],  g_h_lo[B_ * H_];
__device__ __align__(16) bf16 g_x_hi[B_ * C_],  g_x_lo[B_ * C_];
__device__ __align__(16) bf16 g_xd_hi[B_ * C_], g_xd_lo[B_ * C_];
__device__ __align__(16) bf16 g_wh_hi[H_ * H_], g_wh_lo[H_ * H_];
__device__ __align__(16) bf16 g_wo_hi[H_ * H_], g_wo_lo[H_ * H_];
__device__ __align__(16) bf16 g_wx_hi[H_ * C_], g_wx_lo[H_ * C_];
__device__ __align__(16) bf16 g_relu_hi[B_ * H_], g_relu_lo[B_ * H_];
__device__ __align__(16) bf16 g_u_hi[B_ * H_],    g_u_lo[B_ * H_];
__device__ __align__(16) bf16 g_curr_hi[B_ * H_], g_curr_lo[B_ * H_];

// global barrier (prep only)
__device__ unsigned g_bar_count;
__device__ unsigned g_bar_gen;
// per-row-group barriers, cacheline padded (32 uints = 128 B)
__device__ unsigned g_rbar_count[NROWG * 32];
__device__ unsigned g_rbar_gen[NROWG * 32];

extern __shared__ char smem[];

// ---------------- helpers ----------------
__device__ __forceinline__ uint32_t smem_u32(const void* p) {
    uint32_t a;
    asm("{ .reg .u64 t; cvta.to.shared.u64 t, %1; cvt.u32.u64 %0, t; }"
        : "=r"(a) : "l"(p));
    return a;
}
// SW128 swizzle on 128B rows
__device__ __forceinline__ uint32_t swz(int row, int u) {
    return (uint32_t)(row * 128 + ((u ^ (row & 7)) << 4));
}

#define CP_ASYNC16(sa, gp)                                                   \
    asm volatile("cp.async.cg.shared.global [%0], [%1], 16;"                 \
                 :: "r"((uint32_t)(sa)), "l"(gp))
#define CP_COMMIT() asm volatile("cp.async.commit_group;" ::: "memory")
#define CP_WAIT0()  asm volatile("cp.async.wait_group 0;" ::: "memory")
#define CP_WAIT1()  asm volatile("cp.async.wait_group 1;" ::: "memory")

#define LDSM_X4(r, a)                                                        \
    asm volatile("ldmatrix.sync.aligned.m8n8.x4.shared.b16 {%0,%1,%2,%3}, [%4];" \
                 : "=r"((r)[0]), "=r"((r)[1]), "=r"((r)[2]), "=r"((r)[3])    \
                 : "r"(a))
#define LDSM_X2(r, a)                                                        \
    asm volatile("ldmatrix.sync.aligned.m8n8.x2.shared.b16 {%0,%1}, [%2];"   \
                 : "=r"((r)[0]), "=r"((r)[1]) : "r"(a))
#define MMA_BF16(d, a, b)                                                    \
    asm volatile("mma.sync.aligned.m16n8k16.row.col.f32.bf16.bf16.f32 "      \
                 "{%0,%1,%2,%3}, {%4,%5,%6,%7}, {%8,%9}, {%0,%1,%2,%3};"     \
                 : "+f"((d)[0]), "+f"((d)[1]), "+f"((d)[2]), "+f"((d)[3])    \
                 : "r"((a)[0]), "r"((a)[1]), "r"((a)[2]), "r"((a)[3]),       \
                   "r"((b)[0]), "r"((b)[1]))

// global barrier (prep only; all 128 CTAs)
__device__ __forceinline__ void gbar(unsigned& gen) {
    __syncthreads();
    if (threadIdx.x == 0) {
        __threadfence();
        unsigned old = atomicAdd(&g_bar_count, 1);
        if (old == NCTA - 1) {
            g_bar_count = 0;
            __threadfence();
            atomicAdd(&g_bar_gen, 1);
        } else {
            while (*((volatile unsigned*)&g_bar_gen) == gen) { }
        }
        __threadfence();
        gen++;
    }
    __syncthreads();
}

// row-group barrier: only the 16 CTAs sharing blockIdx.x
__device__ __forceinline__ void rbar(int rg, unsigned& gen) {
    __syncthreads();
    if (threadIdx.x == 0) {
        __threadfence();
        unsigned old = atomicAdd(&g_rbar_count[rg * 32], 1);
        if (old == RG_CTAS - 1) {
            g_rbar_count[rg * 32] = 0;
            __threadfence();
            atomicAdd(&g_rbar_gen[rg * 32], 1);
        } else {
            while (*((volatile unsigned*)&g_rbar_gen[rg * 32]) == gen) { }
        }
        __threadfence();
        gen++;
    }
    __syncthreads();
}

__device__ __forceinline__ void cvt_split(float v, bf16* hi, bf16* lo, int i) {
    bf16 h = __float2bfloat16(v);
    hi[i] = h;
    lo[i] = __float2bfloat16(v - __bfloat162float(h));
}

// store a pair (v0,v1) as hi/lo bf16x2 at element offset off (L2 path)
__device__ __forceinline__ void st_split_pair(bf16* hi, bf16* lo, size_t off,
                                              float v0, float v1) {
    bf16 h0 = __float2bfloat16(v0), h1 = __float2bfloat16(v1);
    unsigned uh = ((unsigned)__bfloat16_as_ushort(h1) << 16) |
                  (unsigned)__bfloat16_as_ushort(h0);
    bf16 l0 = __float2bfloat16(v0 - __bfloat162float(h0));
    bf16 l1 = __float2bfloat16(v1 - __bfloat162float(h1));
    unsigned ul = ((unsigned)__bfloat16_as_ushort(l1) << 16) |
                  (unsigned)__bfloat16_as_ushort(l0);
    __stcg((unsigned*)(hi + off), uh);
    __stcg((unsigned*)(lo + off), ul);
}

// ---------------------------------------------------------------------------
// NT GEMM partial with TERM-SPLIT accumulators:
//   acc[0] += Ahi*Whi, acc[1] += Alo*Whi, acc[2] += Ahi*Wlo
// A staged per GEMM via cp.async.cg in TWO commit groups: compute on the
// first half while the second lands (wait_group 1 ... wait_group 0).
// 8 warps: warp w -> m-tile (w>>2), n-group (w&3).
// ---------------------------------------------------------------------------
template <int NCH>
__device__ __forceinline__ void gemmT(const bf16* __restrict__ Ahi,
                                      const bf16* __restrict__ Alo,
                                      int strideA, int bm, uint32_t sb,
                                      uint32_t whi, uint32_t wlo,
                                      float (&acc)[3][4]) {
    const int tid = threadIdx.x;
    const int w = tid >> 5, l = tid & 31;
    const int mt = w >> 2, ng = w & 3;
    const int fr = tid >> 3, fu = tid & 7;
    const uint32_t d_a = swz(fr, fu);
    const bf16* gh = Ahi + (size_t)(bm + fr) * strideA + fu * 8;
    const bf16* gl = Alo + (size_t)(bm + fr) * strideA + fu * 8;
    const int lrow = mt * 16 + (l & 15), kh = l >> 4;       // A
    const int brow = ng * 8 + (l & 7), bsel = (l >> 3) & 1; // B
    constexpr int H1 = (NCH > 1) ? NCH / 2 : NCH;           // first half size

    __syncthreads();  // previous GEMM's reads of SM_A complete
#pragma unroll
    for (int c = 0; c < H1; ++c) {
        CP_ASYNC16(sb + SM_A + c * 4096u + d_a, gh + c * 64);
        CP_ASYNC16(sb + SM_ALO + c * 4096u + d_a, gl + c * 64);
    }
    CP_COMMIT();
    if (NCH > 1) {
#pragma unroll
        for (int c = H1; c < NCH; ++c) {
            CP_ASYNC16(sb + SM_A + c * 4096u + d_a, gh + c * 64);
            CP_ASYNC16(sb + SM_ALO + c * 4096u + d_a, gl + c * 64);
        }
        CP_COMMIT();
        CP_WAIT1();   // first half (and any older groups, incl. W) done
    } else {
        CP_WAIT0();
    }
    __syncthreads();  // first half visible to all warps

#pragma unroll
    for (int c = 0; c < NCH; ++c) {
        if (NCH > 1 && c == H1) {
            CP_WAIT0();
            __syncthreads();  // second half visible
        }
        const uint32_t whc = sb + whi + c * 4096u;
        const uint32_t wlc = sb + wlo + c * 4096u;
        const uint32_t ac = sb + SM_A + c * 4096u;
        uint32_t bh[4][2], bl[4][2];
#pragma unroll
        for (int ks = 0; ks < 4; ++ks) {
            const uint32_t boff = swz(brow, ks * 2 + bsel);
            LDSM_X2(bh[ks], whc + boff);
            LDSM_X2(bl[ks], wlc + boff);
        }
#pragma unroll
        for (int ks = 0; ks < 4; ++ks) {
            const uint32_t am = ac + swz(lrow, ks * 2 + kh);
            uint32_t ah[4], al[4];
            LDSM_X4(ah, am);
            LDSM_X4(al, am + 32768u);   // SM_ALO - SM_A
            MMA_BF16(acc[0], ah, bh[ks]);
            MMA_BF16(acc[1], al, bh[ks]);
            MMA_BF16(acc[2], ah, bl[ks]);
        }
    }
}

__device__ __forceinline__ float fin(const float (&a)[3][4], int i) {
    return (a[0][i] + a[1][i]) + a[2][i];
}

// load one resident W slice (rows bn..bn+31, K as SW128 chunk tiles), cp.async
__device__ __forceinline__ void load_w(const bf16* __restrict__ src,
                                       uint32_t sb, uint32_t soff, int bn, int K) {
    const int tid = threadIdx.x;
    const int nu = (K / 64) * 32 * 8;
    for (int e = tid; e < nu; e += TPB) {
        int kc = e >> 8;
        int r = (e >> 3) & 31;
        int j = e & 7;
        CP_ASYNC16(sb + soff + kc * 4096 + swz(r, j),
                   src + (size_t)(bn + r) * K + kc * 64 + j * 8);
    }
}

// ---------------------------------------------------------------------------
__global__ void __launch_bounds__(TPB, 1) cde_kernel(
    const float* __restrict__ tptr, const float* __restrict__ tobs,
    const float* __restrict__ coeffs, const float* __restrict__ dcoeffs,
    const float* __restrict__ h, const float* __restrict__ wx,
    const float* __restrict__ wh, const float* __restrict__ wout,
    const float* __restrict__ b0, const float* __restrict__ b1,
    float* __restrict__ out) {
    const int tid = threadIdx.x;
    const int w = tid >> 5, l = tid & 31;
    const int mt = w >> 2, ng = w & 3;
    const int gid = l >> 2;
    const int rg = blockIdx.x;            // row group 0..7
    const int bm = blockIdx.x * 32;
    const int bn = blockIdx.y * 32;
    const uint32_t sb = smem_u32(smem);

    unsigned ggen = 0, gen = 0;
    if (tid == 0) {
        ggen = *((volatile unsigned*)&g_bar_gen);
        gen = *((volatile unsigned*)&g_rbar_gen[rg * 32]);
    }

    // ---- Phase -1: spline + fp32 -> bf16 hi/lo splits (grid-flat) ----
    {
        const int gt = (blockIdx.y * gridDim.x + blockIdx.x) * TPB + tid;
        float tv = tptr[0];
        int idx = 0;
        for (int i = 0; i < NKNOTS; i++) idx += (tobs[i] <= tv) ? 1 : 0;
        idx = min(max(idx - 1, 0), NKNOTS - 2);
        const float dt = tv - tobs[idx];
        for (int i = gt; i < B_ * C_; i += GTH) {
            int b = i / C_, c = i % C_;
            size_t base = ((size_t)(b * (NKNOTS - 1) + idx)) * 4 * C_ + c;
            float v = coeffs[base] + dt * (coeffs[base + C_] +
                      dt * (coeffs[base + 2 * C_] + dt * coeffs[base + 3 * C_]));
            cvt_split(v, g_x_hi, g_x_lo, i);
            v = dcoeffs[base] + dt * (dcoeffs[base + C_] +
                dt * (dcoeffs[base + 2 * C_] + dt * dcoeffs[base + 3 * C_]));
            cvt_split(v, g_xd_hi, g_xd_lo, i);
        }
        for (int i = gt; i < B_ * H_; i += GTH) cvt_split(h[i], g_h_hi, g_h_lo, i);
        for (int i = gt; i < H_ * H_; i += GTH) cvt_split(wh[i], g_wh_hi, g_wh_lo, i);
        for (int i = gt; i < H_ * H_; i += GTH) cvt_split(wout[i], g_wo_hi, g_wo_lo, i);
        for (int i = gt; i < H_ * C_; i += GTH) cvt_split(wx[i], g_wx_hi, g_wx_lo, i);
    }
    gbar(ggen);   // only global barrier

    // ---- resident W tiles for this CTA's 32 cols ----
    load_w(g_wh_hi, sb, SM_WHH, bn, H_);
    load_w(g_wh_lo, sb, SM_WHL, bn, H_);
    load_w(g_wo_hi, sb, SM_WOH, bn, H_);
    load_w(g_wo_lo, sb, SM_WOL, bn, H_);
    load_w(g_wx_hi, sb, SM_WXH, bn, C_);
    load_w(g_wx_lo, sb, SM_WXL, bn, C_);
    CP_COMMIT();  // drained by the first gemmT's wait before any ldsm

    const int col0 = bn + ng * 8 + (l & 3) * 2;
    const float bc0 = b0[col0], bc1 = b0[col0 + 1];
    const float bz0 = b1[col0], bz1 = b1[col0 + 1];
    int rw[2];
    rw[0] = mt * 16 + gid;
    rw[1] = mt * 16 + 8 + gid;

    float sdr[4], sdt[4], hd[4];

    // ---- L1: acc = h@wh^T + x@wx^T ; aw = xdot@wx^T ----
    {
        float a[3][4] = {}, aw[3][4] = {};
        gemmT<8>(g_h_hi, g_h_lo, H_, bm, sb, SM_WHH, SM_WHL, a);
        gemmT<1>(g_x_hi, g_x_lo, C_, bm, sb, SM_WXH, SM_WXL, a);
        gemmT<1>(g_xd_hi, g_xd_lo, C_, bm, sb, SM_WXH, SM_WXL, aw);
#pragma unroll
        for (int p = 0; p < 2; ++p) {
            float v0 = fin(a, p * 2 + 0) + bc0;
            float v1 = fin(a, p * 2 + 1) + bc1;
            size_t off = (size_t)(bm + rw[p]) * H_ + col0;
            st_split_pair(g_relu_hi, g_relu_lo, off, fmaxf(v0, 0.f), fmaxf(v1, 0.f));
            float d0 = 1.0f / (1.0f + expf(-v0));
            float d1 = 1.0f / (1.0f + expf(-v1));
            sdr[p * 2] = d0;
            sdr[p * 2 + 1] = d1;
            st_split_pair(g_u_hi, g_u_lo, off,
                          d0 * fin(aw, p * 2), d1 * fin(aw, p * 2 + 1));
        }
    }
    rbar(rg, gen);

    // ---- Z: z = relu@wout^T ; uq = u0@wout^T ----
    {
        float z[3][4] = {}, q[3][4] = {};
        gemmT<8>(g_relu_hi, g_relu_lo, H_, bm, sb, SM_WOH, SM_WOL, z);
        gemmT<8>(g_u_hi, g_u_lo, H_, bm, sb, SM_WOH, SM_WOL, q);
#pragma unroll
        for (int p = 0; p < 2; ++p) {
            float t0 = tanhf(fin(z, p * 2 + 0) + bz0);
            float t1 = tanhf(fin(z, p * 2 + 1) + bz1);
            float d0 = 1.0f - t0 * t0, d1 = 1.0f - t1 * t1;
            sdt[p * 2] = d0;
            sdt[p * 2 + 1] = d1;
            float v0 = d0 * fin(q, p * 2), v1 = d1 * fin(q, p * 2 + 1);
            hd[p * 2] = v0;
            hd[p * 2 + 1] = v1;
            size_t off = (size_t)(bm + rw[p]) * H_ + col0;
            st_split_pair(g_curr_hi, g_curr_lo, off, v0, v1);
        }
    }
    rbar(rg, gen);

    // ---- 8 von-Neumann iterations ----
    for (int it = 0; it < KTERMS; ++it) {
        {   // u = drelu * (curr @ wh^T)
            float a[3][4] = {};
            gemmT<8>(g_curr_hi, g_curr_lo, H_, bm, sb, SM_WHH, SM_WHL, a);
#pragma unroll
            for (int p = 0; p < 2; ++p) {
                size_t off = (size_t)(bm + rw[p]) * H_ + col0;
                st_split_pair(g_u_hi, g_u_lo, off,
                              sdr[p * 2] * fin(a, p * 2),
                              sdr[p * 2 + 1] * fin(a, p * 2 + 1));
            }
        }
        rbar(rg, gen);
        {   // curr' = dtanh * (u @ wout^T); hdot += curr'
            float c[3][4] = {};
            gemmT<8>(g_u_hi, g_u_lo, H_, bm, sb, SM_WOH, SM_WOL, c);
#pragma unroll
            for (int p = 0; p < 2; ++p) {
                float v0 = sdt[p * 2] * fin(c, p * 2);
                float v1 = sdt[p * 2 + 1] * fin(c, p * 2 + 1);
                hd[p * 2] += v0;
                hd[p * 2 + 1] += v1;
                if (it < KTERMS - 1) {
                    size_t off = (size_t)(bm + rw[p]) * H_ + col0;
                    st_split_pair(g_curr_hi, g_curr_lo, off, v0, v1);
                }
            }
            if (it < KTERMS - 1) rbar(rg, gen);
        }
    }

    // ---- write h_dot (fp32) ----
#pragma unroll
    for (int p = 0; p < 2; ++p) {
        size_t off = (size_t)(bm + rw[p]) * H_ + col0;
        *(float2*)(out + off) = make_float2(hd[p * 2], hd[p * 2 + 1]);
    }
}

// ---------------------------------------------------------------------------
extern "C" void kernel_launch(void* const* d_in, const int* in_sizes, int n_in,
                              void* d_out, int out_size) {
    const float* t      = (const float*)d_in[0];
    const float* h      = (const float*)d_in[1];
    const float* coeffs = (const float*)d_in[2];
    const float* dcoeff = (const float*)d_in[3];
    const float* tobs   = (const float*)d_in[4];
    const float* wx     = (const float*)d_in[5];
    const float* wh     = (const float*)d_in[6];
    const float* wout   = (const float*)d_in[7];
    const float* b0     = (const float*)d_in[8];
    const float* b1     = (const float*)d_in[9];
    float* out = (float*)d_out;

    cudaFuncSetAttribute(cde_kernel, cudaFuncAttributeMaxDynamicSharedMemorySize,
                         SM_TOTAL);
    dim3 grid(NROWG, RG_CTAS);  // 8 x 16 = 128 CTAs, single wave
    cde_kernel<<<grid, TPB, SM_TOTAL>>>(t, tobs, coeffs, dcoeff, h, wx, wh,
                                        wout, b0, b1, out);
}